// round 2
// baseline (speedup 1.0000x reference)
#include <cuda_runtime.h>
#include <cuda_bf16.h>

// ---------------------------------------------------------------------------
// TGAT restructured:
//   qk[b,h,m]  = sum_d (Wq_h q0)[d] * Wk[h*192+d, m]   (fold: Wqk = Wk_h^T Wq_h)
//   logit[h,n] = qk_h . k0[n] / sqrt(192), mask, softmax
//   ctx[h,m]   = sum_n attn[h,n] k0[n,m]
//   out[j]     = sum_{h,m} Wov[j, h*384+m] ctx[h,m] + bo   (fold: Wov = Wo_h Wv_h)
//   res=out+q0 ; LN ; x=[ln,src] ; y = W2 relu(W1 x + b1) + b2
// ---------------------------------------------------------------------------

#define Bsz 4096
#define Nn  64
#define Mm  384

// scratch (static device arrays; no allocations allowed)
__device__ __align__(16) float g_wqk[768 * 256];     // folded Wk^T Wq (zero cols of q0 removed)
__device__ __align__(16) float g_wov[384 * 768];     // folded Wo Wv
__device__ __align__(16) float g_q0p[Bsz * 256];     // [src | src_t]
__device__ __align__(16) float g_qk [Bsz * 768];
__device__ __align__(16) float g_ctx[Bsz * 768];
__device__ __align__(16) float g_out[Bsz * 384];
__device__ __align__(16) float g_x  [Bsz * 512];
__device__ __align__(16) float g_h  [Bsz * 128];

// ---------------------------------------------------------------------------
// Fold 1: Wqk[h*384+m, c] = sum_d Wk[h*192+d, m] * Wq[h*192+d, m'(c)]
//   c in [0,256): m' = c<128 ? c : c+128   (skip zero slice of q0)
// grid (16, 48), block (16,16)
// ---------------------------------------------------------------------------
__global__ void fold_qk_kernel(const float* __restrict__ Wk,
                               const float* __restrict__ Wq,
                               float* __restrict__ Wqk)
{
    __shared__ float sK[16][16];
    __shared__ float sQ[16][16];
    int tx = threadIdx.x, ty = threadIdx.y;
    int r0 = blockIdx.y * 16;            // row in [0,768)
    int c0 = blockIdx.x * 16;            // col in [0,256)
    int h    = r0 / 384;
    int mloc = r0 % 384;
    int c = c0 + tx;
    int mprime = (c < 128) ? c : c + 128;
    float acc = 0.f;
    for (int dt = 0; dt < 192; dt += 16) {
        int d = h * 192 + dt + ty;
        sK[ty][tx] = Wk[d * 384 + (mloc + tx)];
        sQ[ty][tx] = Wq[d * 384 + mprime];
        __syncthreads();
        #pragma unroll
        for (int kk = 0; kk < 16; kk++)
            acc = fmaf(sK[kk][ty], sQ[kk][tx], acc);
        __syncthreads();
    }
    Wqk[(r0 + ty) * 256 + c0 + tx] = acc;
}

// ---------------------------------------------------------------------------
// Fold 2: Wov[j, h*384+m] = sum_d Wo[j, h*192+d] * Wv[h*192+d, m]
// grid (48, 24), block (16,16)
// ---------------------------------------------------------------------------
__global__ void fold_ov_kernel(const float* __restrict__ Wo,
                               const float* __restrict__ Wv,
                               float* __restrict__ Wov)
{
    __shared__ float sO[16][16];
    __shared__ float sV[16][16];
    int tx = threadIdx.x, ty = threadIdx.y;
    int r0 = blockIdx.y * 16;            // j in [0,384)
    int c0 = blockIdx.x * 16;            // col in [0,768)
    int h  = c0 / 384;
    int m0 = c0 % 384;
    float acc = 0.f;
    for (int dt = 0; dt < 192; dt += 16) {
        sO[ty][tx] = Wo[(r0 + ty) * 384 + (h * 192 + dt + tx)];
        sV[ty][tx] = Wv[(h * 192 + dt + ty) * 384 + (m0 + tx)];
        __syncthreads();
        #pragma unroll
        for (int kk = 0; kk < 16; kk++)
            acc = fmaf(sO[ty][kk], sV[kk][tx], acc);
        __syncthreads();
    }
    Wov[(r0 + ty) * 768 + c0 + tx] = acc;
}

// ---------------------------------------------------------------------------
// build q0 packed: [src(128) | src_t(128)]  -> (4096 x 256)
// ---------------------------------------------------------------------------
__global__ void build_q0_kernel(const float* __restrict__ src,
                                const float* __restrict__ src_t,
                                float* __restrict__ q0p)
{
    long idx = (long)blockIdx.x * 256 + threadIdx.x;   // 4096*256 total
    long b = idx >> 8;
    int  c = (int)(idx & 255);
    float v = (c < 128) ? src[b * 128 + c] : src_t[b * 128 + (c - 128)];
    q0p[idx] = v;
}

// ---------------------------------------------------------------------------
// Generic fp32 NT GEMM: C[M,N] = A[M,K] @ B[N,K]^T (+bias)(+relu)
// BM=BN=64, BK=16, 256 threads, 4x4 per thread. M%64==0, N%64==0, K%16==0.
// ---------------------------------------------------------------------------
__global__ void gemm_nt_kernel(const float* __restrict__ A,
                               const float* __restrict__ B,
                               const float* __restrict__ bias,
                               float* __restrict__ C,
                               int M, int N, int K, int relu)
{
    __shared__ float As[16][64];
    __shared__ float Bs[16][64];
    int tid = threadIdx.x;
    int row0 = blockIdx.y * 64;
    int col0 = blockIdx.x * 64;
    int lr = tid >> 2;              // 0..63
    int lk = (tid & 3) << 2;        // 0,4,8,12
    int tr = tid >> 4;              // 0..15
    int tc = tid & 15;              // 0..15
    float acc[4][4] = {};
    const float* Ap = A + (long)(row0 + lr) * K + lk;
    const float* Bp = B + (long)(col0 + lr) * K + lk;
    for (int k0 = 0; k0 < K; k0 += 16) {
        float4 a = *(const float4*)(Ap + k0);
        float4 bq = *(const float4*)(Bp + k0);
        As[lk + 0][lr] = a.x;  As[lk + 1][lr] = a.y;
        As[lk + 2][lr] = a.z;  As[lk + 3][lr] = a.w;
        Bs[lk + 0][lr] = bq.x; Bs[lk + 1][lr] = bq.y;
        Bs[lk + 2][lr] = bq.z; Bs[lk + 3][lr] = bq.w;
        __syncthreads();
        #pragma unroll
        for (int kk = 0; kk < 16; kk++) {
            float av[4], bv[4];
            #pragma unroll
            for (int i = 0; i < 4; i++) av[i] = As[kk][tr * 4 + i];
            #pragma unroll
            for (int j = 0; j < 4; j++) bv[j] = Bs[kk][tc * 4 + j];
            #pragma unroll
            for (int i = 0; i < 4; i++)
                #pragma unroll
                for (int j = 0; j < 4; j++)
                    acc[i][j] = fmaf(av[i], bv[j], acc[i][j]);
        }
        __syncthreads();
    }
    #pragma unroll
    for (int i = 0; i < 4; i++) {
        long r = row0 + tr * 4 + i;
        #pragma unroll
        for (int j = 0; j < 4; j++) {
            int c = col0 + tc * 4 + j;
            float v = acc[i][j];
            if (bias) v += bias[c];
            if (relu) v = fmaxf(v, 0.f);
            C[r * N + c] = v;
        }
    }
}

// ---------------------------------------------------------------------------
// Attention per batch: 1 CTA / batch, 256 threads.
// smem: sk0[64*384] + sqk[768] + slog[128] + sattn[128]  = 102400 B
// mask is read as 4-byte elements (harness converts bool -> int32/float32;
// nonzero bit pattern == True for both encodings).
// ---------------------------------------------------------------------------
__global__ void attn_kernel(const float* __restrict__ seq,
                            const float* __restrict__ seq_e,
                            const float* __restrict__ seq_t,
                            const int* __restrict__ mask,
                            const float* __restrict__ qk,
                            float* __restrict__ ctx,
                            float* __restrict__ attn_out)
{
    extern __shared__ float sm[];
    float* sk0   = sm;                 // 64*384
    float* sqk   = sm + 64 * 384;      // 768
    float* slog  = sqk + 768;          // 128
    float* sattn = slog + 128;         // 128

    long b = blockIdx.x;
    int tid = threadIdx.x;

    // load k0 = [seq | seq_e | seq_t] rows into smem (float4, coalesced per part)
    for (int idx = tid; idx < 64 * 96; idx += 256) {
        int n   = idx / 96;
        int c4  = idx % 96;
        int part = c4 >> 5;
        int off  = (c4 & 31) << 2;
        const float* p = (part == 0) ? seq : ((part == 1) ? seq_e : seq_t);
        float4 v = *(const float4*)(p + (b * 64 + n) * 128 + off);
        *(float4*)(sk0 + n * 384 + part * 128 + off) = v;
    }
    for (int j = tid; j < 768; j += 256) sqk[j] = qk[b * 768 + j];
    __syncthreads();

    int wid = tid >> 5, lane = tid & 31;

    // logits: 128 jobs (h,n), one warp per job
    for (int job = wid; job < 128; job += 8) {
        int h = job >> 6, n = job & 63;
        const float* kr = sk0 + n * 384;
        const float* qr = sqk + h * 384;
        float s = 0.f;
        #pragma unroll
        for (int it = 0; it < 3; it++) {
            int m = it * 128 + lane * 4;
            float4 kv = *(const float4*)(kr + m);
            float4 qv = *(const float4*)(qr + m);
            s += kv.x * qv.x + kv.y * qv.y + kv.z * qv.z + kv.w * qv.w;
        }
        #pragma unroll
        for (int o = 16; o; o >>= 1) s += __shfl_xor_sync(0xffffffffu, s, o);
        if (lane == 0) {
            s *= 0.07216878364870323f;   // 1/sqrt(192)
            if (mask[b * 64 + n] != 0) s = -1e10f;
            slog[job] = s;
        }
    }
    __syncthreads();

    // softmax over n per head (warps 0,1)
    if (wid < 2) {
        int h = wid;
        float v0 = slog[h * 64 + lane];
        float v1 = slog[h * 64 + 32 + lane];
        float mx = fmaxf(v0, v1);
        #pragma unroll
        for (int o = 16; o; o >>= 1) mx = fmaxf(mx, __shfl_xor_sync(0xffffffffu, mx, o));
        float e0 = expf(v0 - mx);
        float e1 = expf(v1 - mx);
        float s = e0 + e1;
        #pragma unroll
        for (int o = 16; o; o >>= 1) s += __shfl_xor_sync(0xffffffffu, s, o);
        float inv = 1.f / s;
        float a0 = e0 * inv, a1 = e1 * inv;
        sattn[h * 64 + lane]      = a0;
        sattn[h * 64 + 32 + lane] = a1;
        attn_out[((long)h * Bsz + b) * 64 + lane]      = a0;
        attn_out[((long)h * Bsz + b) * 64 + 32 + lane] = a1;
    }
    __syncthreads();

    // ctx[h*384+m] = sum_n attn[h,n] * k0[n,m]  (192 float4 jobs)
    if (tid < 192) {
        int h  = tid / 96;
        int m4 = tid % 96;
        float4 acc = make_float4(0.f, 0.f, 0.f, 0.f);
        const float* kp = sk0 + m4 * 4;
        #pragma unroll 8
        for (int n = 0; n < 64; n++) {
            float a = sattn[h * 64 + n];
            float4 kv = *(const float4*)(kp + n * 384);
            acc.x = fmaf(a, kv.x, acc.x);
            acc.y = fmaf(a, kv.y, acc.y);
            acc.z = fmaf(a, kv.z, acc.z);
            acc.w = fmaf(a, kv.w, acc.w);
        }
        *(float4*)(ctx + b * 768 + tid * 4) = acc;
    }
}

// ---------------------------------------------------------------------------
// res = out + q0 ; LayerNorm(384) ; x = [ln_out | src] (512)
// 8 warps -> 8 batches per CTA, grid 512
// ---------------------------------------------------------------------------
__global__ void ln_kernel(const float* __restrict__ outp,
                          const float* __restrict__ src,
                          const float* __restrict__ src_t,
                          const float* __restrict__ g,
                          const float* __restrict__ bta,
                          float* __restrict__ x)
{
    int wid = threadIdx.x >> 5, lane = threadIdx.x & 31;
    long b = (long)blockIdx.x * 8 + wid;
    float r[12];
    float sum = 0.f, sq = 0.f;
    #pragma unroll
    for (int i = 0; i < 12; i++) {
        int m = lane + i * 32;
        float v = outp[b * 384 + m];
        if (i < 4)       v += src[b * 128 + m];
        else if (i >= 8) v += src_t[b * 128 + (m - 256)];
        r[i] = v;
        sum += v;
        sq  = fmaf(v, v, sq);
    }
    #pragma unroll
    for (int o = 16; o; o >>= 1) {
        sum += __shfl_xor_sync(0xffffffffu, sum, o);
        sq  += __shfl_xor_sync(0xffffffffu, sq, o);
    }
    float mu  = sum * (1.f / 384.f);
    float var = sq * (1.f / 384.f) - mu * mu;
    float inv = rsqrtf(var + 1e-5f);
    #pragma unroll
    for (int i = 0; i < 12; i++) {
        int m = lane + i * 32;
        x[b * 512 + m] = (r[i] - mu) * inv * g[m] + bta[m];
    }
    #pragma unroll
    for (int i = 0; i < 4; i++) {
        int m = lane + i * 32;
        x[b * 512 + 384 + m] = src[b * 128 + m];
    }
}

// ---------------------------------------------------------------------------

extern "C" void kernel_launch(void* const* d_in, const int* in_sizes, int n_in,
                              void* d_out, int out_size)
{
    const float* src   = (const float*)d_in[0];
    const float* src_t = (const float*)d_in[1];
    const float* seq   = (const float*)d_in[2];
    const float* seq_t = (const float*)d_in[3];
    const float* seq_e = (const float*)d_in[4];
    const int*   mask  = (const int*)d_in[5];      // bool -> int32/float32 by harness; !=0 test covers both
    const float* Wq   = (const float*)d_in[6];
    const float* Wk   = (const float*)d_in[7];
    const float* Wv   = (const float*)d_in[8];
    const float* Wo   = (const float*)d_in[9];
    const float* bo   = (const float*)d_in[10];
    const float* ln_g = (const float*)d_in[11];
    const float* ln_b = (const float*)d_in[12];
    const float* W1   = (const float*)d_in[13];
    const float* b1   = (const float*)d_in[14];
    const float* W2   = (const float*)d_in[15];
    const float* b2   = (const float*)d_in[16];

    float* y        = (float*)d_out;               // (4096,128)
    float* attn_out = (float*)d_out + Bsz * 128;   // (H*B, 64)

    // resolve device-symbol addresses (host side of __device__ arrays)
    float *p_wqk, *p_wov, *p_q0p, *p_qk, *p_ctx, *p_out, *p_x, *p_h;
    cudaGetSymbolAddress((void**)&p_wqk, g_wqk);
    cudaGetSymbolAddress((void**)&p_wov, g_wov);
    cudaGetSymbolAddress((void**)&p_q0p, g_q0p);
    cudaGetSymbolAddress((void**)&p_qk,  g_qk);
    cudaGetSymbolAddress((void**)&p_ctx, g_ctx);
    cudaGetSymbolAddress((void**)&p_out, g_out);
    cudaGetSymbolAddress((void**)&p_x,   g_x);
    cudaGetSymbolAddress((void**)&p_h,   g_h);

    const int ATTN_SMEM = (64 * 384 + 768 + 128 + 128) * 4;  // 102400 B
    cudaFuncSetAttribute(attn_kernel, cudaFuncAttributeMaxDynamicSharedMemorySize, ATTN_SMEM);

    // 1. folds (independent)
    fold_qk_kernel<<<dim3(16, 48), dim3(16, 16)>>>(Wk, Wq, p_wqk);
    fold_ov_kernel<<<dim3(48, 24), dim3(16, 16)>>>(Wo, Wv, p_wov);

    // 2. packed q0
    build_q0_kernel<<<Bsz, 256>>>(src, src_t, p_q0p);

    // 3. qk = q0p @ Wqk^T   (4096 x 768, K=256)
    gemm_nt_kernel<<<dim3(768 / 64, Bsz / 64), 256>>>(p_q0p, p_wqk, nullptr, p_qk,
                                                      Bsz, 768, 256, 0);

    // 4. attention (streams seq/seq_e/seq_t once; writes attn output + ctx)
    attn_kernel<<<Bsz, 256, ATTN_SMEM>>>(seq, seq_e, seq_t, mask, p_qk, p_ctx, attn_out);

    // 5. out = ctx @ Wov^T + bo   (4096 x 384, K=768)
    gemm_nt_kernel<<<dim3(384 / 64, Bsz / 64), 256>>>(p_ctx, p_wov, bo, p_out,
                                                      Bsz, 384, 768, 0);

    // 6. residual + LN + concat src -> x (4096 x 512)
    ln_kernel<<<Bsz / 8, 256>>>(p_out, src, src_t, ln_g, ln_b, p_x);

    // 7. FFN
    gemm_nt_kernel<<<dim3(128 / 64, Bsz / 64), 256>>>(p_x, W1, b1, p_h,
                                                      Bsz, 128, 512, 1);
    gemm_nt_kernel<<<dim3(128 / 64, Bsz / 64), 256>>>(p_h, W2, b2, y,
                                                      Bsz, 128, 128, 0);
}

// round 3
// speedup vs baseline: 1.0569x; 1.0569x over previous
#include <cuda_runtime.h>
#include <cuda_bf16.h>

// ---------------------------------------------------------------------------
// TGAT restructured (unchanged math):
//   qk[b,h,m]  = sum_d (Wq_h q0)[d] * Wk[h*192+d, m]   (fold: Wqk = Wk_h^T Wq_h)
//   logit[h,n] = qk_h . k0[n] / sqrt(192), mask, softmax
//   ctx[h,m]   = sum_n attn[h,n] k0[n,m]
//   out[j]     = sum_{h,m} Wov[j, h*384+m] ctx[h,m] + bo   (fold: Wov = Wo_h Wv_h)
//   res=out+q0 ; LN ; x=[ln,src] ; y = W2 relu(W1 x + b1) + b2
// ---------------------------------------------------------------------------

#define Bsz 4096
#define Nn  64
#define Mm  384

__device__ __align__(16) float g_wqk[768 * 256];
__device__ __align__(16) float g_wov[384 * 768];
__device__ __align__(16) float g_q0p[Bsz * 256];
__device__ __align__(16) float g_qk [Bsz * 768];
__device__ __align__(16) float g_ctx[Bsz * 768];
__device__ __align__(16) float g_out[Bsz * 384];
__device__ __align__(16) float g_x  [Bsz * 512];
__device__ __align__(16) float g_h  [Bsz * 128];

// ---------------------------------------------------------------------------
// Fold 1: Wqk[h*384+m, c] = sum_d Wk[h*192+d, m] * Wq[h*192+d, m'(c)]
// ---------------------------------------------------------------------------
__global__ void fold_qk_kernel(const float* __restrict__ Wk,
                               const float* __restrict__ Wq,
                               float* __restrict__ Wqk)
{
    __shared__ float sK[16][16];
    __shared__ float sQ[16][16];
    int tx = threadIdx.x, ty = threadIdx.y;
    int r0 = blockIdx.y * 16;
    int c0 = blockIdx.x * 16;
    int h    = r0 / 384;
    int mloc = r0 % 384;
    int c = c0 + tx;
    int mprime = (c < 128) ? c : c + 128;
    float acc = 0.f;
    for (int dt = 0; dt < 192; dt += 16) {
        int d = h * 192 + dt + ty;
        sK[ty][tx] = Wk[d * 384 + (mloc + tx)];
        sQ[ty][tx] = Wq[d * 384 + mprime];
        __syncthreads();
        #pragma unroll
        for (int kk = 0; kk < 16; kk++)
            acc = fmaf(sK[kk][ty], sQ[kk][tx], acc);
        __syncthreads();
    }
    Wqk[(r0 + ty) * 256 + c0 + tx] = acc;
}

// ---------------------------------------------------------------------------
// Fold 2: Wov[j, h*384+m] = sum_d Wo[j, h*192+d] * Wv[h*192+d, m]
// ---------------------------------------------------------------------------
__global__ void fold_ov_kernel(const float* __restrict__ Wo,
                               const float* __restrict__ Wv,
                               float* __restrict__ Wov)
{
    __shared__ float sO[16][16];
    __shared__ float sV[16][16];
    int tx = threadIdx.x, ty = threadIdx.y;
    int r0 = blockIdx.y * 16;
    int c0 = blockIdx.x * 16;
    int h  = c0 / 384;
    int m0 = c0 % 384;
    float acc = 0.f;
    for (int dt = 0; dt < 192; dt += 16) {
        sO[ty][tx] = Wo[(r0 + ty) * 384 + (h * 192 + dt + tx)];
        sV[ty][tx] = Wv[(h * 192 + dt + ty) * 384 + (m0 + tx)];
        __syncthreads();
        #pragma unroll
        for (int kk = 0; kk < 16; kk++)
            acc = fmaf(sO[ty][kk], sV[kk][tx], acc);
        __syncthreads();
    }
    Wov[(r0 + ty) * 768 + c0 + tx] = acc;
}

// ---------------------------------------------------------------------------
__global__ void build_q0_kernel(const float* __restrict__ src,
                                const float* __restrict__ src_t,
                                float* __restrict__ q0p)
{
    long idx = (long)blockIdx.x * 256 + threadIdx.x;
    long b = idx >> 8;
    int  c = (int)(idx & 255);
    float v = (c < 128) ? src[b * 128 + c] : src_t[b * 128 + (c - 128)];
    q0p[idx] = v;
}

// ---------------------------------------------------------------------------
// High-throughput fp32 NT GEMM: C[M,N] = A[M,K] @ B[N,K]^T (+bias)(+relu)
// Tile 128x64, BK=16, 256 threads, 8x4 micro-tile, double-buffered smem.
// Requires: M%128==0, N%64==0, K%16==0, K>=32.
// ---------------------------------------------------------------------------
__global__ void gemm_nt_128x64(const float* __restrict__ A,
                               const float* __restrict__ B,
                               const float* __restrict__ bias,
                               float* __restrict__ C,
                               int M, int N, int K, int relu)
{
    __shared__ float As[2][16][128];
    __shared__ float Bs[2][16][64];
    const int tid = threadIdx.x;
    const int row0 = blockIdx.y * 128;
    const int col0 = blockIdx.x * 64;

    // A loader: 2 float4/thread; row = tid>>1, k-offset = (tid&1)*8
    const int arow  = tid >> 1;
    const int akoff = (tid & 1) << 3;
    const float* Ap = A + (long)(row0 + arow) * K + akoff;
    // B loader: 1 float4/thread; row = tid>>2, k-offset = (tid&3)*4
    const int brow  = tid >> 2;
    const int bkoff = (tid & 3) << 2;
    const float* Bp = B + (long)(col0 + brow) * K + bkoff;

    const int tr = (tid >> 4) << 3;   // 0..120
    const int tc = (tid & 15) << 2;   // 0..60

    float acc[8][4] = {};

    // preload tile 0
    {
        float4 a0 = *(const float4*)(Ap);
        float4 a1 = *(const float4*)(Ap + 4);
        float4 b0 = *(const float4*)(Bp);
        As[0][akoff + 0][arow] = a0.x; As[0][akoff + 1][arow] = a0.y;
        As[0][akoff + 2][arow] = a0.z; As[0][akoff + 3][arow] = a0.w;
        As[0][akoff + 4][arow] = a1.x; As[0][akoff + 5][arow] = a1.y;
        As[0][akoff + 6][arow] = a1.z; As[0][akoff + 7][arow] = a1.w;
        Bs[0][bkoff + 0][brow] = b0.x; Bs[0][bkoff + 1][brow] = b0.y;
        Bs[0][bkoff + 2][brow] = b0.z; Bs[0][bkoff + 3][brow] = b0.w;
    }
    __syncthreads();

    int buf = 0;
    for (int k0 = 0; k0 < K; k0 += 16) {
        const bool has_next = (k0 + 16) < K;
        float4 na0, na1, nb0;
        if (has_next) {
            na0 = *(const float4*)(Ap + k0 + 16);
            na1 = *(const float4*)(Ap + k0 + 20);
            nb0 = *(const float4*)(Bp + k0 + 16);
        }
        #pragma unroll
        for (int kk = 0; kk < 16; kk++) {
            float ra[8], rb[4];
            *(float4*)(ra)     = *(const float4*)&As[buf][kk][tr];
            *(float4*)(ra + 4) = *(const float4*)&As[buf][kk][tr + 4];
            *(float4*)(rb)     = *(const float4*)&Bs[buf][kk][tc];
            #pragma unroll
            for (int i = 0; i < 8; i++)
                #pragma unroll
                for (int j = 0; j < 4; j++)
                    acc[i][j] = fmaf(ra[i], rb[j], acc[i][j]);
        }
        if (has_next) {
            const int nb = buf ^ 1;
            As[nb][akoff + 0][arow] = na0.x; As[nb][akoff + 1][arow] = na0.y;
            As[nb][akoff + 2][arow] = na0.z; As[nb][akoff + 3][arow] = na0.w;
            As[nb][akoff + 4][arow] = na1.x; As[nb][akoff + 5][arow] = na1.y;
            As[nb][akoff + 6][arow] = na1.z; As[nb][akoff + 7][arow] = na1.w;
            Bs[nb][bkoff + 0][brow] = nb0.x; Bs[nb][bkoff + 1][brow] = nb0.y;
            Bs[nb][bkoff + 2][brow] = nb0.z; Bs[nb][bkoff + 3][brow] = nb0.w;
            __syncthreads();
            buf = nb;
        }
    }

    float bv[4] = {0.f, 0.f, 0.f, 0.f};
    if (bias) {
        float4 bb = *(const float4*)(bias + col0 + tc);
        bv[0] = bb.x; bv[1] = bb.y; bv[2] = bb.z; bv[3] = bb.w;
    }
    #pragma unroll
    for (int i = 0; i < 8; i++) {
        long r = row0 + tr + i;
        float4 v;
        v.x = acc[i][0] + bv[0];
        v.y = acc[i][1] + bv[1];
        v.z = acc[i][2] + bv[2];
        v.w = acc[i][3] + bv[3];
        if (relu) {
            v.x = fmaxf(v.x, 0.f); v.y = fmaxf(v.y, 0.f);
            v.z = fmaxf(v.z, 0.f); v.w = fmaxf(v.w, 0.f);
        }
        *(float4*)(C + r * N + col0 + tc) = v;
    }
}

// ---------------------------------------------------------------------------
// Small fp32 NT GEMM (64x64, 4x4) — used for FFN where N=128 limits tiles.
// ---------------------------------------------------------------------------
__global__ void gemm_nt_kernel(const float* __restrict__ A,
                               const float* __restrict__ B,
                               const float* __restrict__ bias,
                               float* __restrict__ C,
                               int M, int N, int K, int relu)
{
    __shared__ float As[16][64];
    __shared__ float Bs[16][64];
    int tid = threadIdx.x;
    int row0 = blockIdx.y * 64;
    int col0 = blockIdx.x * 64;
    int lr = tid >> 2;
    int lk = (tid & 3) << 2;
    int tr = tid >> 4;
    int tc = tid & 15;
    float acc[4][4] = {};
    const float* Ap = A + (long)(row0 + lr) * K + lk;
    const float* Bp = B + (long)(col0 + lr) * K + lk;
    for (int k0 = 0; k0 < K; k0 += 16) {
        float4 a = *(const float4*)(Ap + k0);
        float4 bq = *(const float4*)(Bp + k0);
        As[lk + 0][lr] = a.x;  As[lk + 1][lr] = a.y;
        As[lk + 2][lr] = a.z;  As[lk + 3][lr] = a.w;
        Bs[lk + 0][lr] = bq.x; Bs[lk + 1][lr] = bq.y;
        Bs[lk + 2][lr] = bq.z; Bs[lk + 3][lr] = bq.w;
        __syncthreads();
        #pragma unroll
        for (int kk = 0; kk < 16; kk++) {
            float av[4], bvv[4];
            #pragma unroll
            for (int i = 0; i < 4; i++) av[i] = As[kk][tr * 4 + i];
            #pragma unroll
            for (int j = 0; j < 4; j++) bvv[j] = Bs[kk][tc * 4 + j];
            #pragma unroll
            for (int i = 0; i < 4; i++)
                #pragma unroll
                for (int j = 0; j < 4; j++)
                    acc[i][j] = fmaf(av[i], bvv[j], acc[i][j]);
        }
        __syncthreads();
    }
    #pragma unroll
    for (int i = 0; i < 4; i++) {
        long r = row0 + tr * 4 + i;
        #pragma unroll
        for (int j = 0; j < 4; j++) {
            int c = col0 + tc * 4 + j;
            float v = acc[i][j];
            if (bias) v += bias[c];
            if (relu) v = fmaxf(v, 0.f);
            C[r * N + c] = v;
        }
    }
}

// ---------------------------------------------------------------------------
// Attention per batch: 1 CTA / batch, 256 threads. smem 102400 B.
// ---------------------------------------------------------------------------
__global__ void attn_kernel(const float* __restrict__ seq,
                            const float* __restrict__ seq_e,
                            const float* __restrict__ seq_t,
                            const int* __restrict__ mask,
                            const float* __restrict__ qk,
                            float* __restrict__ ctx,
                            float* __restrict__ attn_out)
{
    extern __shared__ float sm[];
    float* sk0   = sm;
    float* sqk   = sm + 64 * 384;
    float* slog  = sqk + 768;
    float* sattn = slog + 128;

    long b = blockIdx.x;
    int tid = threadIdx.x;

    for (int idx = tid; idx < 64 * 96; idx += 256) {
        int n   = idx / 96;
        int c4  = idx % 96;
        int part = c4 >> 5;
        int off  = (c4 & 31) << 2;
        const float* p = (part == 0) ? seq : ((part == 1) ? seq_e : seq_t);
        float4 v = *(const float4*)(p + (b * 64 + n) * 128 + off);
        *(float4*)(sk0 + n * 384 + part * 128 + off) = v;
    }
    for (int j = tid; j < 768; j += 256) sqk[j] = qk[b * 768 + j];
    __syncthreads();

    int wid = tid >> 5, lane = tid & 31;

    for (int job = wid; job < 128; job += 8) {
        int h = job >> 6, n = job & 63;
        const float* kr = sk0 + n * 384;
        const float* qr = sqk + h * 384;
        float s = 0.f;
        #pragma unroll
        for (int it = 0; it < 3; it++) {
            int m = it * 128 + lane * 4;
            float4 kv = *(const float4*)(kr + m);
            float4 qv = *(const float4*)(qr + m);
            s += kv.x * qv.x + kv.y * qv.y + kv.z * qv.z + kv.w * qv.w;
        }
        #pragma unroll
        for (int o = 16; o; o >>= 1) s += __shfl_xor_sync(0xffffffffu, s, o);
        if (lane == 0) {
            s *= 0.07216878364870323f;
            if (mask[b * 64 + n] != 0) s = -1e10f;
            slog[job] = s;
        }
    }
    __syncthreads();

    if (wid < 2) {
        int h = wid;
        float v0 = slog[h * 64 + lane];
        float v1 = slog[h * 64 + 32 + lane];
        float mx = fmaxf(v0, v1);
        #pragma unroll
        for (int o = 16; o; o >>= 1) mx = fmaxf(mx, __shfl_xor_sync(0xffffffffu, mx, o));
        float e0 = expf(v0 - mx);
        float e1 = expf(v1 - mx);
        float s = e0 + e1;
        #pragma unroll
        for (int o = 16; o; o >>= 1) s += __shfl_xor_sync(0xffffffffu, s, o);
        float inv = 1.f / s;
        float a0 = e0 * inv, a1 = e1 * inv;
        sattn[h * 64 + lane]      = a0;
        sattn[h * 64 + 32 + lane] = a1;
        attn_out[((long)h * Bsz + b) * 64 + lane]      = a0;
        attn_out[((long)h * Bsz + b) * 64 + 32 + lane] = a1;
    }
    __syncthreads();

    if (tid < 192) {
        int h  = tid / 96;
        int m4 = tid % 96;
        float4 acc = make_float4(0.f, 0.f, 0.f, 0.f);
        const float* kp = sk0 + m4 * 4;
        #pragma unroll 8
        for (int n = 0; n < 64; n++) {
            float a = sattn[h * 64 + n];
            float4 kv = *(const float4*)(kp + n * 384);
            acc.x = fmaf(a, kv.x, acc.x);
            acc.y = fmaf(a, kv.y, acc.y);
            acc.z = fmaf(a, kv.z, acc.z);
            acc.w = fmaf(a, kv.w, acc.w);
        }
        *(float4*)(ctx + b * 768 + tid * 4) = acc;
    }
}

// ---------------------------------------------------------------------------
__global__ void ln_kernel(const float* __restrict__ outp,
                          const float* __restrict__ src,
                          const float* __restrict__ src_t,
                          const float* __restrict__ g,
                          const float* __restrict__ bta,
                          float* __restrict__ x)
{
    int wid = threadIdx.x >> 5, lane = threadIdx.x & 31;
    long b = (long)blockIdx.x * 8 + wid;
    float r[12];
    float sum = 0.f, sq = 0.f;
    #pragma unroll
    for (int i = 0; i < 12; i++) {
        int m = lane + i * 32;
        float v = outp[b * 384 + m];
        if (i < 4)       v += src[b * 128 + m];
        else if (i >= 8) v += src_t[b * 128 + (m - 256)];
        r[i] = v;
        sum += v;
        sq  = fmaf(v, v, sq);
    }
    #pragma unroll
    for (int o = 16; o; o >>= 1) {
        sum += __shfl_xor_sync(0xffffffffu, sum, o);
        sq  += __shfl_xor_sync(0xffffffffu, sq, o);
    }
    float mu  = sum * (1.f / 384.f);
    float var = sq * (1.f / 384.f) - mu * mu;
    float inv = rsqrtf(var + 1e-5f);
    #pragma unroll
    for (int i = 0; i < 12; i++) {
        int m = lane + i * 32;
        x[b * 512 + m] = (r[i] - mu) * inv * g[m] + bta[m];
    }
    #pragma unroll
    for (int i = 0; i < 4; i++) {
        int m = lane + i * 32;
        x[b * 512 + 384 + m] = src[b * 128 + m];
    }
}

// ---------------------------------------------------------------------------

extern "C" void kernel_launch(void* const* d_in, const int* in_sizes, int n_in,
                              void* d_out, int out_size)
{
    const float* src   = (const float*)d_in[0];
    const float* src_t = (const float*)d_in[1];
    const float* seq   = (const float*)d_in[2];
    const float* seq_t = (const float*)d_in[3];
    const float* seq_e = (const float*)d_in[4];
    const int*   mask  = (const int*)d_in[5];
    const float* Wq   = (const float*)d_in[6];
    const float* Wk   = (const float*)d_in[7];
    const float* Wv   = (const float*)d_in[8];
    const float* Wo   = (const float*)d_in[9];
    const float* bo   = (const float*)d_in[10];
    const float* ln_g = (const float*)d_in[11];
    const float* ln_b = (const float*)d_in[12];
    const float* W1   = (const float*)d_in[13];
    const float* b1   = (const float*)d_in[14];
    const float* W2   = (const float*)d_in[15];
    const float* b2   = (const float*)d_in[16];

    float* y        = (float*)d_out;
    float* attn_out = (float*)d_out + Bsz * 128;

    float *p_wqk, *p_wov, *p_q0p, *p_qk, *p_ctx, *p_out, *p_x, *p_h;
    cudaGetSymbolAddress((void**)&p_wqk, g_wqk);
    cudaGetSymbolAddress((void**)&p_wov, g_wov);
    cudaGetSymbolAddress((void**)&p_q0p, g_q0p);
    cudaGetSymbolAddress((void**)&p_qk,  g_qk);
    cudaGetSymbolAddress((void**)&p_ctx, g_ctx);
    cudaGetSymbolAddress((void**)&p_out, g_out);
    cudaGetSymbolAddress((void**)&p_x,   g_x);
    cudaGetSymbolAddress((void**)&p_h,   g_h);

    const int ATTN_SMEM = (64 * 384 + 768 + 128 + 128) * 4;
    cudaFuncSetAttribute(attn_kernel, cudaFuncAttributeMaxDynamicSharedMemorySize, ATTN_SMEM);

    // 1. folds
    fold_qk_kernel<<<dim3(16, 48), dim3(16, 16)>>>(Wk, Wq, p_wqk);
    fold_ov_kernel<<<dim3(48, 24), dim3(16, 16)>>>(Wo, Wv, p_wov);

    // 2. packed q0
    build_q0_kernel<<<Bsz, 256>>>(src, src_t, p_q0p);

    // 3. qk = q0p @ Wqk^T   (4096 x 768, K=256)  — 128x64 tiles, grid (12,32)
    gemm_nt_128x64<<<dim3(768 / 64, Bsz / 128), 256>>>(p_q0p, p_wqk, nullptr, p_qk,
                                                       Bsz, 768, 256, 0);

    // 4. attention
    attn_kernel<<<Bsz, 256, ATTN_SMEM>>>(seq, seq_e, seq_t, mask, p_qk, p_ctx, attn_out);

    // 5. out = ctx @ Wov^T + bo   (4096 x 384, K=768) — grid (6,32)
    gemm_nt_128x64<<<dim3(384 / 64, Bsz / 128), 256>>>(p_ctx, p_wov, bo, p_out,
                                                       Bsz, 384, 768, 0);

    // 6. residual + LN + concat
    ln_kernel<<<Bsz / 8, 256>>>(p_out, src, src_t, ln_g, ln_b, p_x);

    // 7. FFN (small N — 64x64 kernel keeps 128 CTAs in flight)
    gemm_nt_kernel<<<dim3(128 / 64, Bsz / 64), 256>>>(p_x, W1, b1, p_h,
                                                      Bsz, 128, 512, 1);
    gemm_nt_kernel<<<dim3(128 / 64, Bsz / 64), 256>>>(p_h, W2, b2, y,
                                                      Bsz, 128, 128, 0);
}

// round 4
// speedup vs baseline: 1.1403x; 1.0788x over previous
#include <cuda_runtime.h>
#include <cuda_bf16.h>

// ---------------------------------------------------------------------------
// TGAT restructured (math unchanged):
//   qk = [src|src_t] @ Wqk^T          (Wqk = fold of Wq,Wk; K=256)
//   logits/softmax/ctx fused per batch (k0 kept in smem, read once per phase)
//   out = ctx @ Wov^T (+bo in LN)     (Wov = fold of Wo,Wv; split-K=2)
//   res=out+q0 ; LN ; x=[ln,src] ; y = W2 relu(W1 x + b1) + b2
// ---------------------------------------------------------------------------

#define Bsz 4096

__device__ __align__(16) float g_wqk[768 * 256];
__device__ __align__(16) float g_wov[384 * 768];
__device__ __align__(16) float g_qk [Bsz * 768];
__device__ __align__(16) float g_ctx[Bsz * 768];
__device__ __align__(16) float g_out[2 * Bsz * 384];   // split-K partials
__device__ __align__(16) float g_x  [Bsz * 512];
__device__ __align__(16) float g_h  [Bsz * 128];

// ---------------------------------------------------------------------------
// Fold 1: Wqk[h*384+m, c] = sum_d Wk[h*192+d, m] * Wq[h*192+d, m'(c)]
// ---------------------------------------------------------------------------
__global__ void fold_qk_kernel(const float* __restrict__ Wk,
                               const float* __restrict__ Wq,
                               float* __restrict__ Wqk)
{
    __shared__ float sK[16][16];
    __shared__ float sQ[16][16];
    int tx = threadIdx.x, ty = threadIdx.y;
    int r0 = blockIdx.y * 16;
    int c0 = blockIdx.x * 16;
    int h    = r0 / 384;
    int mloc = r0 % 384;
    int c = c0 + tx;
    int mprime = (c < 128) ? c : c + 128;
    float acc = 0.f;
    for (int dt = 0; dt < 192; dt += 16) {
        int d = h * 192 + dt + ty;
        sK[ty][tx] = Wk[d * 384 + (mloc + tx)];
        sQ[ty][tx] = Wq[d * 384 + mprime];
        __syncthreads();
        #pragma unroll
        for (int kk = 0; kk < 16; kk++)
            acc = fmaf(sK[kk][ty], sQ[kk][tx], acc);
        __syncthreads();
    }
    Wqk[(r0 + ty) * 256 + c0 + tx] = acc;
}

// ---------------------------------------------------------------------------
// Fold 2: Wov[j, h*384+m] = sum_d Wo[j, h*192+d] * Wv[h*192+d, m]
// ---------------------------------------------------------------------------
__global__ void fold_ov_kernel(const float* __restrict__ Wo,
                               const float* __restrict__ Wv,
                               float* __restrict__ Wov)
{
    __shared__ float sO[16][16];
    __shared__ float sV[16][16];
    int tx = threadIdx.x, ty = threadIdx.y;
    int r0 = blockIdx.y * 16;
    int c0 = blockIdx.x * 16;
    int h  = c0 / 384;
    int m0 = c0 % 384;
    float acc = 0.f;
    for (int dt = 0; dt < 192; dt += 16) {
        sO[ty][tx] = Wo[(r0 + ty) * 384 + (h * 192 + dt + tx)];
        sV[ty][tx] = Wv[(h * 192 + dt + ty) * 384 + (m0 + tx)];
        __syncthreads();
        #pragma unroll
        for (int kk = 0; kk < 16; kk++)
            acc = fmaf(sO[ty][kk], sV[kk][tx], acc);
        __syncthreads();
    }
    Wov[(r0 + ty) * 768 + c0 + tx] = acc;
}

// ---------------------------------------------------------------------------
// fp32 NT GEMM: 128x128 tile, BK=16, 256 threads, 8x8 micro, double-buffered.
// C[M,N] = A[M,K] @ B[N,K]^T. Balanced LDS:FMA (64B LDS / 64 FMA per k-step).
// Concat mode: if A1 != nullptr, logical A row = [A0 row(128) | A1 row(128)].
// Split-K via gridDim.z: slice Kslice=K/nz, output slab z at C + z*M*N.
// Requires M%128==0, N%128==0, Kslice%16==0.
// ---------------------------------------------------------------------------
__global__ void __launch_bounds__(256, 2)
gemm_nt_128x128(const float* __restrict__ A0, const float* __restrict__ A1,
                const float* __restrict__ B, const float* __restrict__ bias,
                float* __restrict__ C, int M, int N, int K, int relu)
{
    __shared__ float As[2][16][128];
    __shared__ float Bs[2][16][128];
    const int tid  = threadIdx.x;
    const int row0 = blockIdx.y * 128;
    const int col0 = blockIdx.x * 128;
    const int Kslice = K / gridDim.z;
    const int kbase  = blockIdx.z * Kslice;
    float* Cz = C + (size_t)blockIdx.z * (size_t)M * N;

    const int lrow = tid >> 1;           // 0..127 (row within tile, A and B)
    const int koff = (tid & 1) << 3;     // 0 or 8

    const int tr = (tid >> 4) << 3;      // 0..120
    const int tc = (tid & 15) << 3;      // 0..120

    float acc[8][8] = {};

    const float* Bp = B + (long)(col0 + lrow) * K + kbase + koff;

    float4 a0, a1, b0, b1;

    // A address helper (concat-aware). Chunk [kk,kk+8) never crosses the 128
    // boundary because kk is always a multiple of 8.
    auto loadA = [&](int k) {
        int kk = kbase + k + koff;
        const float* p;
        long row = row0 + lrow;
        if (A1) p = (kk < 128) ? (A0 + row * 128 + kk)
                               : (A1 + row * 128 + (kk - 128));
        else    p = A0 + row * (long)K + kk;
        a0 = *(const float4*)p;
        a1 = *(const float4*)(p + 4);
    };
    auto loadB = [&](int k) {
        b0 = *(const float4*)(Bp + k);
        b1 = *(const float4*)(Bp + k + 4);
    };
    auto stAB = [&](int buf) {
        As[buf][koff + 0][lrow] = a0.x; As[buf][koff + 1][lrow] = a0.y;
        As[buf][koff + 2][lrow] = a0.z; As[buf][koff + 3][lrow] = a0.w;
        As[buf][koff + 4][lrow] = a1.x; As[buf][koff + 5][lrow] = a1.y;
        As[buf][koff + 6][lrow] = a1.z; As[buf][koff + 7][lrow] = a1.w;
        Bs[buf][koff + 0][lrow] = b0.x; Bs[buf][koff + 1][lrow] = b0.y;
        Bs[buf][koff + 2][lrow] = b0.z; Bs[buf][koff + 3][lrow] = b0.w;
        Bs[buf][koff + 4][lrow] = b1.x; Bs[buf][koff + 5][lrow] = b1.y;
        Bs[buf][koff + 6][lrow] = b1.z; Bs[buf][koff + 7][lrow] = b1.w;
    };

    loadA(0); loadB(0);
    stAB(0);
    __syncthreads();

    int buf = 0;
    for (int k0 = 0; k0 < Kslice; k0 += 16) {
        const bool nxt = (k0 + 16) < Kslice;
        if (nxt) { loadA(k0 + 16); loadB(k0 + 16); }
        #pragma unroll
        for (int kk = 0; kk < 16; kk++) {
            float ra[8], rb[8];
            *(float4*)(ra)     = *(const float4*)&As[buf][kk][tr];
            *(float4*)(ra + 4) = *(const float4*)&As[buf][kk][tr + 4];
            *(float4*)(rb)     = *(const float4*)&Bs[buf][kk][tc];
            *(float4*)(rb + 4) = *(const float4*)&Bs[buf][kk][tc + 4];
            #pragma unroll
            for (int i = 0; i < 8; i++)
                #pragma unroll
                for (int j = 0; j < 8; j++)
                    acc[i][j] = fmaf(ra[i], rb[j], acc[i][j]);
        }
        if (nxt) {
            buf ^= 1;
            stAB(buf);
            __syncthreads();
        }
    }

    float bv[8] = {};
    if (bias && blockIdx.z == 0) {
        float4 x0 = *(const float4*)(bias + col0 + tc);
        float4 x1 = *(const float4*)(bias + col0 + tc + 4);
        bv[0]=x0.x; bv[1]=x0.y; bv[2]=x0.z; bv[3]=x0.w;
        bv[4]=x1.x; bv[5]=x1.y; bv[6]=x1.z; bv[7]=x1.w;
    }
    #pragma unroll
    for (int i = 0; i < 8; i++) {
        long r = row0 + tr + i;
        float o[8];
        #pragma unroll
        for (int j = 0; j < 8; j++) {
            float v = acc[i][j] + bv[j];
            if (relu) v = fmaxf(v, 0.f);
            o[j] = v;
        }
        *(float4*)(Cz + r * N + col0 + tc)     = *(float4*)(o);
        *(float4*)(Cz + r * N + col0 + tc + 4) = *(float4*)(o + 4);
    }
}

// ---------------------------------------------------------------------------
// Small fp32 NT GEMM (64x64, 4x4) — FFN (N=128 limits tile count).
// ---------------------------------------------------------------------------
__global__ void gemm_nt_kernel(const float* __restrict__ A,
                               const float* __restrict__ B,
                               const float* __restrict__ bias,
                               float* __restrict__ C,
                               int M, int N, int K, int relu)
{
    __shared__ float As[16][64];
    __shared__ float Bs[16][64];
    int tid = threadIdx.x;
    int row0 = blockIdx.y * 64;
    int col0 = blockIdx.x * 64;
    int lr = tid >> 2;
    int lk = (tid & 3) << 2;
    int tr = tid >> 4;
    int tc = tid & 15;
    float acc[4][4] = {};
    const float* Ap = A + (long)(row0 + lr) * K + lk;
    const float* Bp = B + (long)(col0 + lr) * K + lk;
    for (int k0 = 0; k0 < K; k0 += 16) {
        float4 a = *(const float4*)(Ap + k0);
        float4 bq = *(const float4*)(Bp + k0);
        As[lk + 0][lr] = a.x;  As[lk + 1][lr] = a.y;
        As[lk + 2][lr] = a.z;  As[lk + 3][lr] = a.w;
        Bs[lk + 0][lr] = bq.x; Bs[lk + 1][lr] = bq.y;
        Bs[lk + 2][lr] = bq.z; Bs[lk + 3][lr] = bq.w;
        __syncthreads();
        #pragma unroll
        for (int kk = 0; kk < 16; kk++) {
            float av[4], bvv[4];
            #pragma unroll
            for (int i = 0; i < 4; i++) av[i] = As[kk][tr * 4 + i];
            #pragma unroll
            for (int j = 0; j < 4; j++) bvv[j] = Bs[kk][tc * 4 + j];
            #pragma unroll
            for (int i = 0; i < 4; i++)
                #pragma unroll
                for (int j = 0; j < 4; j++)
                    acc[i][j] = fmaf(av[i], bvv[j], acc[i][j]);
        }
        __syncthreads();
    }
    #pragma unroll
    for (int i = 0; i < 4; i++) {
        long r = row0 + tr * 4 + i;
        #pragma unroll
        for (int j = 0; j < 4; j++) {
            int c = col0 + tc * 4 + j;
            float v = acc[i][j];
            if (bias) v += bias[c];
            if (relu) v = fmaxf(v, 0.f);
            C[r * N + c] = v;
        }
    }
}

// ---------------------------------------------------------------------------
// Attention per batch: 1 CTA / batch, 256 threads.
// Both heads computed per k0 read: k0 smem traffic ~1x per phase.
// smem floats: sk0 24576 + sqk 768 + slog 128 + sattn 128 + spart 768 = 26368
// ---------------------------------------------------------------------------
__global__ void attn_kernel(const float* __restrict__ seq,
                            const float* __restrict__ seq_e,
                            const float* __restrict__ seq_t,
                            const int* __restrict__ mask,
                            const float* __restrict__ qk,
                            float* __restrict__ ctx,
                            float* __restrict__ attn_out)
{
    extern __shared__ float sm[];
    float* sk0   = sm;                    // 64*384
    float* sqk   = sm + 24576;            // 768
    float* slog  = sqk + 768;             // 128
    float* sattn = slog + 128;            // 128
    float* spart = sattn + 128;           // 96*8

    long b = blockIdx.x;
    int tid = threadIdx.x;
    int wid = tid >> 5, lane = tid & 31;

    // load k0 = [seq | seq_e | seq_t] rows (float4, coalesced per part)
    for (int idx = tid; idx < 64 * 96; idx += 256) {
        int n   = idx / 96;
        int c4  = idx % 96;
        int part = c4 >> 5;
        int off  = (c4 & 31) << 2;
        const float* p = (part == 0) ? seq : ((part == 1) ? seq_e : seq_t);
        float4 v = *(const float4*)(p + (b * 64 + n) * 128 + off);
        *(float4*)(sk0 + n * 384 + part * 128 + off) = v;
    }
    for (int j = tid; j < 768; j += 256) sqk[j] = qk[b * 768 + j];
    __syncthreads();

    // --- logits: q preloaded to regs (reused across jobs), both heads per k read
    {
        float q0r[12], q1r[12];
        #pragma unroll
        for (int it = 0; it < 3; it++) {
            float4 v0 = *(const float4*)(sqk + it * 128 + lane * 4);
            float4 v1 = *(const float4*)(sqk + 384 + it * 128 + lane * 4);
            q0r[it*4+0]=v0.x; q0r[it*4+1]=v0.y; q0r[it*4+2]=v0.z; q0r[it*4+3]=v0.w;
            q1r[it*4+0]=v1.x; q1r[it*4+1]=v1.y; q1r[it*4+2]=v1.z; q1r[it*4+3]=v1.w;
        }
        for (int n = wid; n < 64; n += 8) {
            const float* kr = sk0 + n * 384;
            float s0 = 0.f, s1 = 0.f;
            #pragma unroll
            for (int it = 0; it < 3; it++) {
                float4 kv = *(const float4*)(kr + it * 128 + lane * 4);
                s0 = fmaf(kv.x, q0r[it*4+0], s0); s1 = fmaf(kv.x, q1r[it*4+0], s1);
                s0 = fmaf(kv.y, q0r[it*4+1], s0); s1 = fmaf(kv.y, q1r[it*4+1], s1);
                s0 = fmaf(kv.z, q0r[it*4+2], s0); s1 = fmaf(kv.z, q1r[it*4+2], s1);
                s0 = fmaf(kv.w, q0r[it*4+3], s0); s1 = fmaf(kv.w, q1r[it*4+3], s1);
            }
            #pragma unroll
            for (int o = 16; o; o >>= 1) {
                s0 += __shfl_xor_sync(0xffffffffu, s0, o);
                s1 += __shfl_xor_sync(0xffffffffu, s1, o);
            }
            if (lane == 0) {
                s0 *= 0.07216878364870323f;    // 1/sqrt(192)
                s1 *= 0.07216878364870323f;
                if (mask[b * 64 + n] != 0) { s0 = -1e10f; s1 = -1e10f; }
                slog[n]      = s0;
                slog[64 + n] = s1;
            }
        }
    }
    __syncthreads();

    // --- softmax over n per head (warps 0,1)
    if (wid < 2) {
        int h = wid;
        float v0 = slog[h * 64 + lane];
        float v1 = slog[h * 64 + 32 + lane];
        float mx = fmaxf(v0, v1);
        #pragma unroll
        for (int o = 16; o; o >>= 1) mx = fmaxf(mx, __shfl_xor_sync(0xffffffffu, mx, o));
        float e0 = __expf(v0 - mx);
        float e1 = __expf(v1 - mx);
        float s = e0 + e1;
        #pragma unroll
        for (int o = 16; o; o >>= 1) s += __shfl_xor_sync(0xffffffffu, s, o);
        float inv = 1.f / s;
        float a0 = e0 * inv, a1 = e1 * inv;
        sattn[h * 64 + lane]      = a0;
        sattn[h * 64 + 32 + lane] = a1;
        attn_out[((long)h * Bsz + b) * 64 + lane]      = a0;
        attn_out[((long)h * Bsz + b) * 64 + 32 + lane] = a1;
    }
    __syncthreads();

    // --- ctx: both heads per k0 float4 read; 2-way n-split across 192 threads
    float4 a0 = make_float4(0,0,0,0), a1 = make_float4(0,0,0,0);
    int split = 0, m4 = 0;
    if (tid < 192) {
        split = tid >= 96;
        m4 = tid - split * 96;
        const float* kp = sk0 + m4 * 4;
        int n0 = split * 32;
        #pragma unroll 8
        for (int n = n0; n < n0 + 32; n++) {
            float w0 = sattn[n];
            float w1 = sattn[64 + n];
            float4 kv = *(const float4*)(kp + n * 384);
            a0.x = fmaf(w0, kv.x, a0.x); a1.x = fmaf(w1, kv.x, a1.x);
            a0.y = fmaf(w0, kv.y, a0.y); a1.y = fmaf(w1, kv.y, a1.y);
            a0.z = fmaf(w0, kv.z, a0.z); a1.z = fmaf(w1, kv.z, a1.z);
            a0.w = fmaf(w0, kv.w, a0.w); a1.w = fmaf(w1, kv.w, a1.w);
        }
        if (split) {
            *(float4*)(spart + m4 * 8)     = a0;
            *(float4*)(spart + m4 * 8 + 4) = a1;
        }
    }
    __syncthreads();
    if (tid < 96) {
        float4 p0 = *(const float4*)(spart + m4 * 8);
        float4 p1 = *(const float4*)(spart + m4 * 8 + 4);
        a0.x += p0.x; a0.y += p0.y; a0.z += p0.z; a0.w += p0.w;
        a1.x += p1.x; a1.y += p1.y; a1.z += p1.z; a1.w += p1.w;
        *(float4*)(ctx + b * 768 + m4 * 4)       = a0;
        *(float4*)(ctx + b * 768 + 384 + m4 * 4) = a1;
    }
}

// ---------------------------------------------------------------------------
// res = out0 + out1 + bo + q0 ; LayerNorm(384) ; x = [ln_out | src] (512)
// ---------------------------------------------------------------------------
__global__ void ln_kernel(const float* __restrict__ out0,
                          const float* __restrict__ out1,
                          const float* __restrict__ bo,
                          const float* __restrict__ src,
                          const float* __restrict__ src_t,
                          const float* __restrict__ g,
                          const float* __restrict__ bta,
                          float* __restrict__ x)
{
    int wid = threadIdx.x >> 5, lane = threadIdx.x & 31;
    long b = (long)blockIdx.x * 8 + wid;
    float r[12];
    float sum = 0.f, sq = 0.f;
    #pragma unroll
    for (int i = 0; i < 12; i++) {
        int m = lane + i * 32;
        float v = out0[b * 384 + m] + out1[b * 384 + m] + bo[m];
        if (i < 4)       v += src[b * 128 + m];
        else if (i >= 8) v += src_t[b * 128 + (m - 256)];
        r[i] = v;
        sum += v;
        sq  = fmaf(v, v, sq);
    }
    #pragma unroll
    for (int o = 16; o; o >>= 1) {
        sum += __shfl_xor_sync(0xffffffffu, sum, o);
        sq  += __shfl_xor_sync(0xffffffffu, sq, o);
    }
    float mu  = sum * (1.f / 384.f);
    float var = sq * (1.f / 384.f) - mu * mu;
    float inv = rsqrtf(var + 1e-5f);
    #pragma unroll
    for (int i = 0; i < 12; i++) {
        int m = lane + i * 32;
        x[b * 512 + m] = (r[i] - mu) * inv * g[m] + bta[m];
    }
    #pragma unroll
    for (int i = 0; i < 4; i++) {
        int m = lane + i * 32;
        x[b * 512 + 384 + m] = src[b * 128 + m];
    }
}

// ---------------------------------------------------------------------------

extern "C" void kernel_launch(void* const* d_in, const int* in_sizes, int n_in,
                              void* d_out, int out_size)
{
    const float* src   = (const float*)d_in[0];
    const float* src_t = (const float*)d_in[1];
    const float* seq   = (const float*)d_in[2];
    const float* seq_t = (const float*)d_in[3];
    const float* seq_e = (const float*)d_in[4];
    const int*   mask  = (const int*)d_in[5];
    const float* Wq   = (const float*)d_in[6];
    const float* Wk   = (const float*)d_in[7];
    const float* Wv   = (const float*)d_in[8];
    const float* Wo   = (const float*)d_in[9];
    const float* bo   = (const float*)d_in[10];
    const float* ln_g = (const float*)d_in[11];
    const float* ln_b = (const float*)d_in[12];
    const float* W1   = (const float*)d_in[13];
    const float* b1   = (const float*)d_in[14];
    const float* W2   = (const float*)d_in[15];
    const float* b2   = (const float*)d_in[16];

    float* y        = (float*)d_out;
    float* attn_out = (float*)d_out + Bsz * 128;

    float *p_wqk, *p_wov, *p_qk, *p_ctx, *p_out, *p_x, *p_h;
    cudaGetSymbolAddress((void**)&p_wqk, g_wqk);
    cudaGetSymbolAddress((void**)&p_wov, g_wov);
    cudaGetSymbolAddress((void**)&p_qk,  g_qk);
    cudaGetSymbolAddress((void**)&p_ctx, g_ctx);
    cudaGetSymbolAddress((void**)&p_out, g_out);
    cudaGetSymbolAddress((void**)&p_x,   g_x);
    cudaGetSymbolAddress((void**)&p_h,   g_h);

    const int ATTN_SMEM = (64 * 384 + 768 + 128 + 128 + 96 * 8) * 4;  // 105472
    cudaFuncSetAttribute(attn_kernel, cudaFuncAttributeMaxDynamicSharedMemorySize, ATTN_SMEM);

    // 1. folds
    fold_qk_kernel<<<dim3(16, 48), dim3(16, 16)>>>(Wk, Wq, p_wqk);
    fold_ov_kernel<<<dim3(48, 24), dim3(16, 16)>>>(Wo, Wv, p_wov);

    // 2. qk = [src|src_t] @ Wqk^T   (4096 x 768, K=256), concat A-load
    gemm_nt_128x128<<<dim3(768 / 128, Bsz / 128, 1), 256>>>(
        src, src_t, p_wqk, nullptr, p_qk, Bsz, 768, 256, 0);

    // 3. attention
    attn_kernel<<<Bsz, 256, ATTN_SMEM>>>(seq, seq_e, seq_t, mask, p_qk, p_ctx, attn_out);

    // 4. out = ctx @ Wov^T   (4096 x 384, K=768), split-K=2 -> 192 CTAs
    gemm_nt_128x128<<<dim3(384 / 128, Bsz / 128, 2), 256>>>(
        p_ctx, nullptr, p_wov, nullptr, p_out, Bsz, 384, 768, 0);

    // 5. residual (+ bo + both K-split partials) + LN + concat
    ln_kernel<<<Bsz / 8, 256>>>(p_out, p_out + (size_t)Bsz * 384, bo,
                                src, src_t, ln_g, ln_b, p_x);

    // 6. FFN
    gemm_nt_kernel<<<dim3(2, Bsz / 64), 256>>>(p_x, W1, b1, p_h, Bsz, 128, 512, 1);
    gemm_nt_kernel<<<dim3(2, Bsz / 64), 256>>>(p_h, W2, b2, y,  Bsz, 128, 128, 0);
}

// round 5
// speedup vs baseline: 1.5803x; 1.3859x over previous
#include <cuda_runtime.h>
#include <cuda_bf16.h>

// ---------------------------------------------------------------------------
// TGAT restructured (math unchanged):
//   qk = [src|src_t] @ Wqk^T          (Wqk = fold of Wq,Wk; K=256)
//   flash attention, 1 warp / batch: single pass over k0, online softmax
//   out = ctx @ Wov^T (+bo in LN)     (Wov = fold of Wo,Wv; split-K=2)
//   res=out+q0 ; LN ; x=[ln,src] ; y = W2 relu(W1 x + b1) + b2
// ---------------------------------------------------------------------------

#define Bsz 4096

__device__ __align__(16) float g_wqk[768 * 256];
__device__ __align__(16) float g_wov[384 * 768];
__device__ __align__(16) float g_qk [Bsz * 768];
__device__ __align__(16) float g_ctx[Bsz * 768];
__device__ __align__(16) float g_out[2 * Bsz * 384];   // split-K partials
__device__ __align__(16) float g_x  [Bsz * 512];
__device__ __align__(16) float g_h  [Bsz * 128];

// ---------------------------------------------------------------------------
// Fold 1: Wqk[h*384+m, c] = sum_d Wk[h*192+d, m] * Wq[h*192+d, m'(c)]
// ---------------------------------------------------------------------------
__global__ void fold_qk_kernel(const float* __restrict__ Wk,
                               const float* __restrict__ Wq,
                               float* __restrict__ Wqk)
{
    __shared__ float sK[16][16];
    __shared__ float sQ[16][16];
    int tx = threadIdx.x, ty = threadIdx.y;
    int r0 = blockIdx.y * 16;
    int c0 = blockIdx.x * 16;
    int h    = r0 / 384;
    int mloc = r0 % 384;
    int c = c0 + tx;
    int mprime = (c < 128) ? c : c + 128;
    float acc = 0.f;
    for (int dt = 0; dt < 192; dt += 16) {
        int d = h * 192 + dt + ty;
        sK[ty][tx] = Wk[d * 384 + (mloc + tx)];
        sQ[ty][tx] = Wq[d * 384 + mprime];
        __syncthreads();
        #pragma unroll
        for (int kk = 0; kk < 16; kk++)
            acc = fmaf(sK[kk][ty], sQ[kk][tx], acc);
        __syncthreads();
    }
    Wqk[(r0 + ty) * 256 + c0 + tx] = acc;
}

// ---------------------------------------------------------------------------
// Fold 2: Wov[j, h*384+m] = sum_d Wo[j, h*192+d] * Wv[h*192+d, m]
// ---------------------------------------------------------------------------
__global__ void fold_ov_kernel(const float* __restrict__ Wo,
                               const float* __restrict__ Wv,
                               float* __restrict__ Wov)
{
    __shared__ float sO[16][16];
    __shared__ float sV[16][16];
    int tx = threadIdx.x, ty = threadIdx.y;
    int r0 = blockIdx.y * 16;
    int c0 = blockIdx.x * 16;
    int h  = c0 / 384;
    int m0 = c0 % 384;
    float acc = 0.f;
    for (int dt = 0; dt < 192; dt += 16) {
        sO[ty][tx] = Wo[(r0 + ty) * 384 + (h * 192 + dt + tx)];
        sV[ty][tx] = Wv[(h * 192 + dt + ty) * 384 + (m0 + tx)];
        __syncthreads();
        #pragma unroll
        for (int kk = 0; kk < 16; kk++)
            acc = fmaf(sO[ty][kk], sV[kk][tx], acc);
        __syncthreads();
    }
    Wov[(r0 + ty) * 768 + c0 + tx] = acc;
}

// ---------------------------------------------------------------------------
// fp32 NT GEMM: 128x128 tile, BK=16, 256 threads, 8x8 micro, double-buffered.
// Concat mode: if A1 != nullptr, logical A row = [A0 row(128) | A1 row(128)].
// Split-K via gridDim.z; output slab z at C + z*M*N.
// ---------------------------------------------------------------------------
__global__ void __launch_bounds__(256, 2)
gemm_nt_128x128(const float* __restrict__ A0, const float* __restrict__ A1,
                const float* __restrict__ B, const float* __restrict__ bias,
                float* __restrict__ C, int M, int N, int K, int relu)
{
    __shared__ float As[2][16][128];
    __shared__ float Bs[2][16][128];
    const int tid  = threadIdx.x;
    const int row0 = blockIdx.y * 128;
    const int col0 = blockIdx.x * 128;
    const int Kslice = K / gridDim.z;
    const int kbase  = blockIdx.z * Kslice;
    float* Cz = C + (size_t)blockIdx.z * (size_t)M * N;

    const int lrow = tid >> 1;
    const int koff = (tid & 1) << 3;
    const int tr = (tid >> 4) << 3;
    const int tc = (tid & 15) << 3;

    float acc[8][8] = {};

    const float* Bp = B + (long)(col0 + lrow) * K + kbase + koff;

    float4 a0, a1, b0, b1;

    auto loadA = [&](int k) {
        int kk = kbase + k + koff;
        const float* p;
        long row = row0 + lrow;
        if (A1) p = (kk < 128) ? (A0 + row * 128 + kk)
                               : (A1 + row * 128 + (kk - 128));
        else    p = A0 + row * (long)K + kk;
        a0 = *(const float4*)p;
        a1 = *(const float4*)(p + 4);
    };
    auto loadB = [&](int k) {
        b0 = *(const float4*)(Bp + k);
        b1 = *(const float4*)(Bp + k + 4);
    };
    auto stAB = [&](int buf) {
        As[buf][koff + 0][lrow] = a0.x; As[buf][koff + 1][lrow] = a0.y;
        As[buf][koff + 2][lrow] = a0.z; As[buf][koff + 3][lrow] = a0.w;
        As[buf][koff + 4][lrow] = a1.x; As[buf][koff + 5][lrow] = a1.y;
        As[buf][koff + 6][lrow] = a1.z; As[buf][koff + 7][lrow] = a1.w;
        Bs[buf][koff + 0][lrow] = b0.x; Bs[buf][koff + 1][lrow] = b0.y;
        Bs[buf][koff + 2][lrow] = b0.z; Bs[buf][koff + 3][lrow] = b0.w;
        Bs[buf][koff + 4][lrow] = b1.x; Bs[buf][koff + 5][lrow] = b1.y;
        Bs[buf][koff + 6][lrow] = b1.z; Bs[buf][koff + 7][lrow] = b1.w;
    };

    loadA(0); loadB(0);
    stAB(0);
    __syncthreads();

    int buf = 0;
    for (int k0 = 0; k0 < Kslice; k0 += 16) {
        const bool nxt = (k0 + 16) < Kslice;
        if (nxt) { loadA(k0 + 16); loadB(k0 + 16); }
        #pragma unroll
        for (int kk = 0; kk < 16; kk++) {
            float ra[8], rb[8];
            *(float4*)(ra)     = *(const float4*)&As[buf][kk][tr];
            *(float4*)(ra + 4) = *(const float4*)&As[buf][kk][tr + 4];
            *(float4*)(rb)     = *(const float4*)&Bs[buf][kk][tc];
            *(float4*)(rb + 4) = *(const float4*)&Bs[buf][kk][tc + 4];
            #pragma unroll
            for (int i = 0; i < 8; i++)
                #pragma unroll
                for (int j = 0; j < 8; j++)
                    acc[i][j] = fmaf(ra[i], rb[j], acc[i][j]);
        }
        if (nxt) {
            buf ^= 1;
            stAB(buf);
            __syncthreads();
        }
    }

    float bv[8] = {};
    if (bias && blockIdx.z == 0) {
        float4 x0 = *(const float4*)(bias + col0 + tc);
        float4 x1 = *(const float4*)(bias + col0 + tc + 4);
        bv[0]=x0.x; bv[1]=x0.y; bv[2]=x0.z; bv[3]=x0.w;
        bv[4]=x1.x; bv[5]=x1.y; bv[6]=x1.z; bv[7]=x1.w;
    }
    #pragma unroll
    for (int i = 0; i < 8; i++) {
        long r = row0 + tr + i;
        float o[8];
        #pragma unroll
        for (int j = 0; j < 8; j++) {
            float v = acc[i][j] + bv[j];
            if (relu) v = fmaxf(v, 0.f);
            o[j] = v;
        }
        *(float4*)(Cz + r * N + col0 + tc)     = *(float4*)(o);
        *(float4*)(Cz + r * N + col0 + tc + 4) = *(float4*)(o + 4);
    }
}

// ---------------------------------------------------------------------------
// Small fp32 NT GEMM (64x64, 4x4) — FFN (N=128 limits tile count).
// ---------------------------------------------------------------------------
__global__ void gemm_nt_kernel(const float* __restrict__ A,
                               const float* __restrict__ B,
                               const float* __restrict__ bias,
                               float* __restrict__ C,
                               int M, int N, int K, int relu)
{
    __shared__ float As[16][64];
    __shared__ float Bs[16][64];
    int tid = threadIdx.x;
    int row0 = blockIdx.y * 64;
    int col0 = blockIdx.x * 64;
    int lr = tid >> 2;
    int lk = (tid & 3) << 2;
    int tr = tid >> 4;
    int tc = tid & 15;
    float acc[4][4] = {};
    const float* Ap = A + (long)(row0 + lr) * K + lk;
    const float* Bp = B + (long)(col0 + lr) * K + lk;
    for (int k0 = 0; k0 < K; k0 += 16) {
        float4 a = *(const float4*)(Ap + k0);
        float4 bq = *(const float4*)(Bp + k0);
        As[lk + 0][lr] = a.x;  As[lk + 1][lr] = a.y;
        As[lk + 2][lr] = a.z;  As[lk + 3][lr] = a.w;
        Bs[lk + 0][lr] = bq.x; Bs[lk + 1][lr] = bq.y;
        Bs[lk + 2][lr] = bq.z; Bs[lk + 3][lr] = bq.w;
        __syncthreads();
        #pragma unroll
        for (int kk = 0; kk < 16; kk++) {
            float av[4], bvv[4];
            #pragma unroll
            for (int i = 0; i < 4; i++) av[i] = As[kk][tr * 4 + i];
            #pragma unroll
            for (int j = 0; j < 4; j++) bvv[j] = Bs[kk][tc * 4 + j];
            #pragma unroll
            for (int i = 0; i < 4; i++)
                #pragma unroll
                for (int j = 0; j < 4; j++)
                    acc[i][j] = fmaf(av[i], bvv[j], acc[i][j]);
        }
        __syncthreads();
    }
    #pragma unroll
    for (int i = 0; i < 4; i++) {
        long r = row0 + tr * 4 + i;
        #pragma unroll
        for (int j = 0; j < 4; j++) {
            int c = col0 + tc * 4 + j;
            float v = acc[i][j];
            if (bias) v += bias[c];
            if (relu) v = fmaxf(v, 0.f);
            C[r * N + c] = v;
        }
    }
}

// ---------------------------------------------------------------------------
// Flash attention: 1 warp per batch, zero smem, single pass over k0.
// Online softmax for both heads; raw logits kept in regs for attn_sq output.
// Lane l owns m-positions {part*128 + l*4 .. +3} for part=0..2.
// ---------------------------------------------------------------------------
__global__ void __launch_bounds__(128)
attn_flash_kernel(const float* __restrict__ seq,
                  const float* __restrict__ seq_e,
                  const float* __restrict__ seq_t,
                  const int* __restrict__ mask,
                  const float* __restrict__ qk,
                  float* __restrict__ ctx,
                  float* __restrict__ attn_out)
{
    const int lane = threadIdx.x & 31;
    const long b = (long)blockIdx.x * 4 + (threadIdx.x >> 5);

    // q in registers: 3 float4 per head
    float4 q0[3], q1[3];
    {
        const float* qp = qk + b * 768 + lane * 4;
        #pragma unroll
        for (int it = 0; it < 3; it++) {
            q0[it] = *(const float4*)(qp + it * 128);
            q1[it] = *(const float4*)(qp + 384 + it * 128);
        }
    }

    float4 c0[3], c1[3];
    #pragma unroll
    for (int it = 0; it < 3; it++) {
        c0[it] = make_float4(0.f, 0.f, 0.f, 0.f);
        c1[it] = make_float4(0.f, 0.f, 0.f, 0.f);
    }
    float m0 = -1e30f, m1 = -1e30f, l0 = 0.f, l1 = 0.f;
    float lg0[2], lg1[2];   // raw logits; lane holds n = lane and n = lane+32

    const float* p0 = seq   + b * 64 * 128 + lane * 4;
    const float* p1 = seq_e + b * 64 * 128 + lane * 4;
    const float* p2 = seq_t + b * 64 * 128 + lane * 4;
    const int*   mp = mask + b * 64;

    const float SCALE = 0.07216878364870323f;   // 1/sqrt(192)

    #pragma unroll 4
    for (int n = 0; n < 64; n++) {
        float4 k0v = *(const float4*)(p0 + n * 128);
        float4 k1v = *(const float4*)(p1 + n * 128);
        float4 k2v = *(const float4*)(p2 + n * 128);
        int mk = mp[n];

        // dot products (both heads share the k read)
        float s0 = k0v.x * q0[0].x;            float s1 = k0v.x * q1[0].x;
        s0 = fmaf(k0v.y, q0[0].y, s0);         s1 = fmaf(k0v.y, q1[0].y, s1);
        s0 = fmaf(k0v.z, q0[0].z, s0);         s1 = fmaf(k0v.z, q1[0].z, s1);
        s0 = fmaf(k0v.w, q0[0].w, s0);         s1 = fmaf(k0v.w, q1[0].w, s1);
        s0 = fmaf(k1v.x, q0[1].x, s0);         s1 = fmaf(k1v.x, q1[1].x, s1);
        s0 = fmaf(k1v.y, q0[1].y, s0);         s1 = fmaf(k1v.y, q1[1].y, s1);
        s0 = fmaf(k1v.z, q0[1].z, s0);         s1 = fmaf(k1v.z, q1[1].z, s1);
        s0 = fmaf(k1v.w, q0[1].w, s0);         s1 = fmaf(k1v.w, q1[1].w, s1);
        s0 = fmaf(k2v.x, q0[2].x, s0);         s1 = fmaf(k2v.x, q1[2].x, s1);
        s0 = fmaf(k2v.y, q0[2].y, s0);         s1 = fmaf(k2v.y, q1[2].y, s1);
        s0 = fmaf(k2v.z, q0[2].z, s0);         s1 = fmaf(k2v.z, q1[2].z, s1);
        s0 = fmaf(k2v.w, q0[2].w, s0);         s1 = fmaf(k2v.w, q1[2].w, s1);

        #pragma unroll
        for (int o = 16; o; o >>= 1) {
            s0 += __shfl_xor_sync(0xffffffffu, s0, o);
            s1 += __shfl_xor_sync(0xffffffffu, s1, o);
        }
        s0 *= SCALE;
        s1 *= SCALE;
        if (mk != 0) { s0 = -1e10f; s1 = -1e10f; }

        if ((n & 31) == lane) {
            lg0[n >> 5] = s0;
            lg1[n >> 5] = s1;
        }

        // online softmax update, head 0
        float nm0 = fmaxf(m0, s0);
        float r0  = __expf(m0 - nm0);
        float e0  = __expf(s0 - nm0);
        m0 = nm0;
        l0 = fmaf(l0, r0, e0);
        c0[0].x = fmaf(e0, k0v.x, c0[0].x * r0);
        c0[0].y = fmaf(e0, k0v.y, c0[0].y * r0);
        c0[0].z = fmaf(e0, k0v.z, c0[0].z * r0);
        c0[0].w = fmaf(e0, k0v.w, c0[0].w * r0);
        c0[1].x = fmaf(e0, k1v.x, c0[1].x * r0);
        c0[1].y = fmaf(e0, k1v.y, c0[1].y * r0);
        c0[1].z = fmaf(e0, k1v.z, c0[1].z * r0);
        c0[1].w = fmaf(e0, k1v.w, c0[1].w * r0);
        c0[2].x = fmaf(e0, k2v.x, c0[2].x * r0);
        c0[2].y = fmaf(e0, k2v.y, c0[2].y * r0);
        c0[2].z = fmaf(e0, k2v.z, c0[2].z * r0);
        c0[2].w = fmaf(e0, k2v.w, c0[2].w * r0);

        // head 1
        float nm1 = fmaxf(m1, s1);
        float r1  = __expf(m1 - nm1);
        float e1  = __expf(s1 - nm1);
        m1 = nm1;
        l1 = fmaf(l1, r1, e1);
        c1[0].x = fmaf(e1, k0v.x, c1[0].x * r1);
        c1[0].y = fmaf(e1, k0v.y, c1[0].y * r1);
        c1[0].z = fmaf(e1, k0v.z, c1[0].z * r1);
        c1[0].w = fmaf(e1, k0v.w, c1[0].w * r1);
        c1[1].x = fmaf(e1, k1v.x, c1[1].x * r1);
        c1[1].y = fmaf(e1, k1v.y, c1[1].y * r1);
        c1[1].z = fmaf(e1, k1v.z, c1[1].z * r1);
        c1[1].w = fmaf(e1, k1v.w, c1[1].w * r1);
        c1[2].x = fmaf(e1, k2v.x, c1[2].x * r1);
        c1[2].y = fmaf(e1, k2v.y, c1[2].y * r1);
        c1[2].z = fmaf(e1, k2v.z, c1[2].z * r1);
        c1[2].w = fmaf(e1, k2v.w, c1[2].w * r1);
    }

    const float inv0 = 1.f / l0;
    const float inv1 = 1.f / l1;

    // ctx write (coalesced float4)
    {
        float* cp = ctx + b * 768 + lane * 4;
        #pragma unroll
        for (int it = 0; it < 3; it++) {
            float4 v0 = c0[it];
            v0.x *= inv0; v0.y *= inv0; v0.z *= inv0; v0.w *= inv0;
            *(float4*)(cp + it * 128) = v0;
            float4 v1 = c1[it];
            v1.x *= inv1; v1.y *= inv1; v1.z *= inv1; v1.w *= inv1;
            *(float4*)(cp + 384 + it * 128) = v1;
        }
    }

    // attn_sq output: row h*B + b
    attn_out[b * 64 + lane]                     = __expf(lg0[0] - m0) * inv0;
    attn_out[b * 64 + 32 + lane]                = __expf(lg0[1] - m0) * inv0;
    attn_out[((long)Bsz + b) * 64 + lane]       = __expf(lg1[0] - m1) * inv1;
    attn_out[((long)Bsz + b) * 64 + 32 + lane]  = __expf(lg1[1] - m1) * inv1;
}

// ---------------------------------------------------------------------------
// res = out0 + out1 + bo + q0 ; LayerNorm(384) ; x = [ln_out | src] (512)
// ---------------------------------------------------------------------------
__global__ void ln_kernel(const float* __restrict__ out0,
                          const float* __restrict__ out1,
                          const float* __restrict__ bo,
                          const float* __restrict__ src,
                          const float* __restrict__ src_t,
                          const float* __restrict__ g,
                          const float* __restrict__ bta,
                          float* __restrict__ x)
{
    int wid = threadIdx.x >> 5, lane = threadIdx.x & 31;
    long b = (long)blockIdx.x * 8 + wid;
    float r[12];
    float sum = 0.f, sq = 0.f;
    #pragma unroll
    for (int i = 0; i < 12; i++) {
        int m = lane + i * 32;
        float v = out0[b * 384 + m] + out1[b * 384 + m] + bo[m];
        if (i < 4)       v += src[b * 128 + m];
        else if (i >= 8) v += src_t[b * 128 + (m - 256)];
        r[i] = v;
        sum += v;
        sq  = fmaf(v, v, sq);
    }
    #pragma unroll
    for (int o = 16; o; o >>= 1) {
        sum += __shfl_xor_sync(0xffffffffu, sum, o);
        sq  += __shfl_xor_sync(0xffffffffu, sq, o);
    }
    float mu  = sum * (1.f / 384.f);
    float var = sq * (1.f / 384.f) - mu * mu;
    float inv = rsqrtf(var + 1e-5f);
    #pragma unroll
    for (int i = 0; i < 12; i++) {
        int m = lane + i * 32;
        x[b * 512 + m] = (r[i] - mu) * inv * g[m] + bta[m];
    }
    #pragma unroll
    for (int i = 0; i < 4; i++) {
        int m = lane + i * 32;
        x[b * 512 + 384 + m] = src[b * 128 + m];
    }
}

// ---------------------------------------------------------------------------

extern "C" void kernel_launch(void* const* d_in, const int* in_sizes, int n_in,
                              void* d_out, int out_size)
{
    const float* src   = (const float*)d_in[0];
    const float* src_t = (const float*)d_in[1];
    const float* seq   = (const float*)d_in[2];
    const float* seq_t = (const float*)d_in[3];
    const float* seq_e = (const float*)d_in[4];
    const int*   mask  = (const int*)d_in[5];
    const float* Wq   = (const float*)d_in[6];
    const float* Wk   = (const float*)d_in[7];
    const float* Wv   = (const float*)d_in[8];
    const float* Wo   = (const float*)d_in[9];
    const float* bo   = (const float*)d_in[10];
    const float* ln_g = (const float*)d_in[11];
    const float* ln_b = (const float*)d_in[12];
    const float* W1   = (const float*)d_in[13];
    const float* b1   = (const float*)d_in[14];
    const float* W2   = (const float*)d_in[15];
    const float* b2   = (const float*)d_in[16];

    float* y        = (float*)d_out;
    float* attn_out = (float*)d_out + Bsz * 128;

    float *p_wqk, *p_wov, *p_qk, *p_ctx, *p_out, *p_x, *p_h;
    cudaGetSymbolAddress((void**)&p_wqk, g_wqk);
    cudaGetSymbolAddress((void**)&p_wov, g_wov);
    cudaGetSymbolAddress((void**)&p_qk,  g_qk);
    cudaGetSymbolAddress((void**)&p_ctx, g_ctx);
    cudaGetSymbolAddress((void**)&p_out, g_out);
    cudaGetSymbolAddress((void**)&p_x,   g_x);
    cudaGetSymbolAddress((void**)&p_h,   g_h);

    // 1. folds
    fold_qk_kernel<<<dim3(16, 48), dim3(16, 16)>>>(Wk, Wq, p_wqk);
    fold_ov_kernel<<<dim3(48, 24), dim3(16, 16)>>>(Wo, Wv, p_wov);

    // 2. qk = [src|src_t] @ Wqk^T   (4096 x 768, K=256), concat A-load
    gemm_nt_128x128<<<dim3(768 / 128, Bsz / 128, 1), 256>>>(
        src, src_t, p_wqk, nullptr, p_qk, Bsz, 768, 256, 0);

    // 3. flash attention: 1 warp/batch, 4 warps/CTA -> 1024 CTAs
    attn_flash_kernel<<<Bsz / 4, 128>>>(seq, seq_e, seq_t, mask, p_qk, p_ctx, attn_out);

    // 4. out = ctx @ Wov^T   (4096 x 384, K=768), split-K=2 -> 192 CTAs
    gemm_nt_128x128<<<dim3(384 / 128, Bsz / 128, 2), 256>>>(
        p_ctx, nullptr, p_wov, nullptr, p_out, Bsz, 384, 768, 0);

    // 5. residual (+ bo + both K-split partials) + LN + concat
    ln_kernel<<<Bsz / 8, 256>>>(p_out, p_out + (size_t)Bsz * 384, bo,
                                src, src_t, ln_g, ln_b, p_x);

    // 6. FFN
    gemm_nt_kernel<<<dim3(2, Bsz / 64), 256>>>(p_x, W1, b1, p_h, Bsz, 128, 512, 1);
    gemm_nt_kernel<<<dim3(2, Bsz / 64), 256>>>(p_h, W2, b2, y,  Bsz, 128, 128, 0);
}

// round 6
// speedup vs baseline: 1.6166x; 1.0230x over previous
#include <cuda_runtime.h>
#include <cuda_bf16.h>

// ---------------------------------------------------------------------------
// TGAT restructured (math unchanged):
//   qk = [src|src_t] @ Wqk^T       split-K=2, slabs summed in attn load
//   flash attention, 1 warp/batch, online softmax, zero smem
//   out = ctx @ Wov^T              split-K=4, slabs + bo summed in LN
//   res=out+q0 ; LN ; x=[ln,src]
//   h-slabs = x @ W1^T (split-K=2); FFN2 A-load = relu(h0+h1+b1); y = .. @ W2^T + b2
// ---------------------------------------------------------------------------

#define Bsz 4096

__device__ __align__(16) float g_wqk[768 * 256];
__device__ __align__(16) float g_wov[384 * 768];
__device__ __align__(16) float g_qk [2 * Bsz * 768];   // split-K slabs
__device__ __align__(16) float g_ctx[Bsz * 768];
__device__ __align__(16) float g_out[4 * Bsz * 384];   // split-K slabs
__device__ __align__(16) float g_x  [Bsz * 512];
__device__ __align__(16) float g_h  [2 * Bsz * 128];   // split-K slabs

// ---------------------------------------------------------------------------
// Combined folds (one launch):
//   blocks [0,768):    Wqk[r,c] = sum_d Wk[h*192+d, mloc] * Wq[h*192+d, m'(c)]
//   blocks [768,1920): Wov[j,c] = sum_d Wo[j, h*192+d] * Wv[h*192+d, m0]
// ---------------------------------------------------------------------------
__global__ void fold_both_kernel(const float* __restrict__ Wk,
                                 const float* __restrict__ Wq,
                                 const float* __restrict__ Wo,
                                 const float* __restrict__ Wv,
                                 float* __restrict__ Wqk,
                                 float* __restrict__ Wov)
{
    __shared__ float sA[16][16];
    __shared__ float sB[16][16];
    int tx = threadIdx.x, ty = threadIdx.y;
    int bid = blockIdx.x;
    if (bid < 768) {
        // fold_qk: c0 over 256 (16 tiles), r0 over 768 (48 tiles)
        int c0 = (bid & 15) * 16;
        int r0 = (bid >> 4) * 16;
        int h    = r0 / 384;
        int mloc = r0 % 384;
        int c = c0 + tx;
        int mprime = (c < 128) ? c : c + 128;
        float acc = 0.f;
        for (int dt = 0; dt < 192; dt += 16) {
            int d = h * 192 + dt + ty;
            sA[ty][tx] = Wk[d * 384 + (mloc + tx)];
            sB[ty][tx] = Wq[d * 384 + mprime];
            __syncthreads();
            #pragma unroll
            for (int kk = 0; kk < 16; kk++)
                acc = fmaf(sA[kk][ty], sB[kk][tx], acc);
            __syncthreads();
        }
        Wqk[(r0 + ty) * 256 + c0 + tx] = acc;
    } else {
        // fold_ov: c0 over 768 (48 tiles), r0 over 384 (24 tiles)
        int b2 = bid - 768;
        int c0 = (b2 % 48) * 16;
        int r0 = (b2 / 48) * 16;
        int h  = c0 / 384;
        int m0 = c0 % 384;
        float acc = 0.f;
        for (int dt = 0; dt < 192; dt += 16) {
            sA[ty][tx] = Wo[(r0 + ty) * 384 + (h * 192 + dt + tx)];
            sB[ty][tx] = Wv[(h * 192 + dt + ty) * 384 + (m0 + tx)];
            __syncthreads();
            #pragma unroll
            for (int kk = 0; kk < 16; kk++)
                acc = fmaf(sA[ty][kk], sB[kk][tx], acc);
            __syncthreads();
        }
        Wov[(r0 + ty) * 768 + c0 + tx] = acc;
    }
}

// ---------------------------------------------------------------------------
// fp32 NT GEMM: 128x128 tile, BK=16, 256 threads, 8x8 micro, double-buffered.
// Concat mode: if A1 != nullptr, logical A row = [A0 row(128) | A1 row(128)].
// Split-K via gridDim.z; output slab z at C + z*M*N.
// ---------------------------------------------------------------------------
__global__ void __launch_bounds__(256, 2)
gemm_nt_128x128(const float* __restrict__ A0, const float* __restrict__ A1,
                const float* __restrict__ B, const float* __restrict__ bias,
                float* __restrict__ C, int M, int N, int K, int relu)
{
    __shared__ float As[2][16][128];
    __shared__ float Bs[2][16][128];
    const int tid  = threadIdx.x;
    const int row0 = blockIdx.y * 128;
    const int col0 = blockIdx.x * 128;
    const int Kslice = K / gridDim.z;
    const int kbase  = blockIdx.z * Kslice;
    float* Cz = C + (size_t)blockIdx.z * (size_t)M * N;

    const int lrow = tid >> 1;
    const int koff = (tid & 1) << 3;
    const int tr = (tid >> 4) << 3;
    const int tc = (tid & 15) << 3;

    float acc[8][8] = {};

    const float* Bp = B + (long)(col0 + lrow) * K + kbase + koff;

    float4 a0, a1, b0, b1;

    auto loadA = [&](int k) {
        int kk = kbase + k + koff;
        const float* p;
        long row = row0 + lrow;
        if (A1) p = (kk < 128) ? (A0 + row * 128 + kk)
                               : (A1 + row * 128 + (kk - 128));
        else    p = A0 + row * (long)K + kk;
        a0 = *(const float4*)p;
        a1 = *(const float4*)(p + 4);
    };
    auto loadB = [&](int k) {
        b0 = *(const float4*)(Bp + k);
        b1 = *(const float4*)(Bp + k + 4);
    };
    auto stAB = [&](int buf) {
        As[buf][koff + 0][lrow] = a0.x; As[buf][koff + 1][lrow] = a0.y;
        As[buf][koff + 2][lrow] = a0.z; As[buf][koff + 3][lrow] = a0.w;
        As[buf][koff + 4][lrow] = a1.x; As[buf][koff + 5][lrow] = a1.y;
        As[buf][koff + 6][lrow] = a1.z; As[buf][koff + 7][lrow] = a1.w;
        Bs[buf][koff + 0][lrow] = b0.x; Bs[buf][koff + 1][lrow] = b0.y;
        Bs[buf][koff + 2][lrow] = b0.z; Bs[buf][koff + 3][lrow] = b0.w;
        Bs[buf][koff + 4][lrow] = b1.x; Bs[buf][koff + 5][lrow] = b1.y;
        Bs[buf][koff + 6][lrow] = b1.z; Bs[buf][koff + 7][lrow] = b1.w;
    };

    loadA(0); loadB(0);
    stAB(0);
    __syncthreads();

    int buf = 0;
    for (int k0 = 0; k0 < Kslice; k0 += 16) {
        const bool nxt = (k0 + 16) < Kslice;
        if (nxt) { loadA(k0 + 16); loadB(k0 + 16); }
        #pragma unroll
        for (int kk = 0; kk < 16; kk++) {
            float ra[8], rb[8];
            *(float4*)(ra)     = *(const float4*)&As[buf][kk][tr];
            *(float4*)(ra + 4) = *(const float4*)&As[buf][kk][tr + 4];
            *(float4*)(rb)     = *(const float4*)&Bs[buf][kk][tc];
            *(float4*)(rb + 4) = *(const float4*)&Bs[buf][kk][tc + 4];
            #pragma unroll
            for (int i = 0; i < 8; i++)
                #pragma unroll
                for (int j = 0; j < 8; j++)
                    acc[i][j] = fmaf(ra[i], rb[j], acc[i][j]);
        }
        if (nxt) {
            buf ^= 1;
            stAB(buf);
            __syncthreads();
        }
    }

    float bv[8] = {};
    if (bias && blockIdx.z == 0) {
        float4 x0 = *(const float4*)(bias + col0 + tc);
        float4 x1 = *(const float4*)(bias + col0 + tc + 4);
        bv[0]=x0.x; bv[1]=x0.y; bv[2]=x0.z; bv[3]=x0.w;
        bv[4]=x1.x; bv[5]=x1.y; bv[6]=x1.z; bv[7]=x1.w;
    }
    #pragma unroll
    for (int i = 0; i < 8; i++) {
        long r = row0 + tr + i;
        float o[8];
        #pragma unroll
        for (int j = 0; j < 8; j++) {
            float v = acc[i][j] + bv[j];
            if (relu) v = fmaxf(v, 0.f);
            o[j] = v;
        }
        *(float4*)(Cz + r * N + col0 + tc)     = *(float4*)(o);
        *(float4*)(Cz + r * N + col0 + tc + 4) = *(float4*)(o + 4);
    }
}

// ---------------------------------------------------------------------------
// Small fp32 NT GEMM (64x64, 4x4) with split-K slabs and A-combine mode:
//   if A1 != nullptr:  A(i,k) = relu(A0(i,k) + A1(i,k) + ab[k])
// Used for the FFN. C slab z at C + z*M*N.
// ---------------------------------------------------------------------------
__global__ void gemm_nt_64(const float* __restrict__ A0,
                           const float* __restrict__ A1,
                           const float* __restrict__ ab,
                           const float* __restrict__ B,
                           const float* __restrict__ bias,
                           float* __restrict__ C,
                           int M, int N, int K, int relu)
{
    __shared__ float As[16][64];
    __shared__ float Bs[16][64];
    int tid = threadIdx.x;
    int row0 = blockIdx.y * 64;
    int col0 = blockIdx.x * 64;
    const int Kslice = K / gridDim.z;
    const int kbase  = blockIdx.z * Kslice;
    float* Cz = C + (size_t)blockIdx.z * (size_t)M * N;

    int lr = tid >> 2;
    int lk = (tid & 3) << 2;
    int tr = tid >> 4;
    int tc = tid & 15;
    float acc[4][4] = {};
    const float* Ap0 = A0 + (long)(row0 + lr) * K + kbase + lk;
    const float* Ap1 = A1 ? (A1 + (long)(row0 + lr) * K + kbase + lk) : nullptr;
    const float* Bp  = B + (long)(col0 + lr) * K + kbase + lk;
    for (int k0 = 0; k0 < Kslice; k0 += 16) {
        float4 a = *(const float4*)(Ap0 + k0);
        if (Ap1) {
            float4 a2 = *(const float4*)(Ap1 + k0);
            float4 av = *(const float4*)(ab + kbase + lk + k0);
            a.x = fmaxf(a.x + a2.x + av.x, 0.f);
            a.y = fmaxf(a.y + a2.y + av.y, 0.f);
            a.z = fmaxf(a.z + a2.z + av.z, 0.f);
            a.w = fmaxf(a.w + a2.w + av.w, 0.f);
        }
        float4 bq = *(const float4*)(Bp + k0);
        As[lk + 0][lr] = a.x;  As[lk + 1][lr] = a.y;
        As[lk + 2][lr] = a.z;  As[lk + 3][lr] = a.w;
        Bs[lk + 0][lr] = bq.x; Bs[lk + 1][lr] = bq.y;
        Bs[lk + 2][lr] = bq.z; Bs[lk + 3][lr] = bq.w;
        __syncthreads();
        #pragma unroll
        for (int kk = 0; kk < 16; kk++) {
            float av[4], bvv[4];
            #pragma unroll
            for (int i = 0; i < 4; i++) av[i] = As[kk][tr * 4 + i];
            #pragma unroll
            for (int j = 0; j < 4; j++) bvv[j] = Bs[kk][tc * 4 + j];
            #pragma unroll
            for (int i = 0; i < 4; i++)
                #pragma unroll
                for (int j = 0; j < 4; j++)
                    acc[i][j] = fmaf(av[i], bvv[j], acc[i][j]);
        }
        __syncthreads();
    }
    #pragma unroll
    for (int i = 0; i < 4; i++) {
        long r = row0 + tr * 4 + i;
        #pragma unroll
        for (int j = 0; j < 4; j++) {
            int c = col0 + tc * 4 + j;
            float v = acc[i][j];
            if (bias && blockIdx.z == 0) v += bias[c];
            if (relu) v = fmaxf(v, 0.f);
            Cz[r * N + c] = v;
        }
    }
}

// ---------------------------------------------------------------------------
// Flash attention: 1 warp per batch, zero smem, single pass over k0.
// q-load sums the two split-K slabs of qk.
// ---------------------------------------------------------------------------
__global__ void __launch_bounds__(128)
attn_flash_kernel(const float* __restrict__ seq,
                  const float* __restrict__ seq_e,
                  const float* __restrict__ seq_t,
                  const int* __restrict__ mask,
                  const float* __restrict__ qk,
                  float* __restrict__ ctx,
                  float* __restrict__ attn_out)
{
    const int lane = threadIdx.x & 31;
    const long b = (long)blockIdx.x * 4 + (threadIdx.x >> 5);

    // q in registers: 3 float4 per head; combine split-K slabs
    float4 q0[3], q1[3];
    {
        const float* qp  = qk + b * 768 + lane * 4;
        const float* qp2 = qp + (size_t)Bsz * 768;
        #pragma unroll
        for (int it = 0; it < 3; it++) {
            float4 u = *(const float4*)(qp + it * 128);
            float4 v = *(const float4*)(qp2 + it * 128);
            q0[it] = make_float4(u.x + v.x, u.y + v.y, u.z + v.z, u.w + v.w);
            u = *(const float4*)(qp + 384 + it * 128);
            v = *(const float4*)(qp2 + 384 + it * 128);
            q1[it] = make_float4(u.x + v.x, u.y + v.y, u.z + v.z, u.w + v.w);
        }
    }

    float4 c0[3], c1[3];
    #pragma unroll
    for (int it = 0; it < 3; it++) {
        c0[it] = make_float4(0.f, 0.f, 0.f, 0.f);
        c1[it] = make_float4(0.f, 0.f, 0.f, 0.f);
    }
    float m0 = -1e30f, m1 = -1e30f, l0 = 0.f, l1 = 0.f;
    float lg0[2], lg1[2];

    const float* p0 = seq   + b * 64 * 128 + lane * 4;
    const float* p1 = seq_e + b * 64 * 128 + lane * 4;
    const float* p2 = seq_t + b * 64 * 128 + lane * 4;
    const int*   mp = mask + b * 64;

    const float SCALE = 0.07216878364870323f;   // 1/sqrt(192)

    #pragma unroll 4
    for (int n = 0; n < 64; n++) {
        float4 k0v = *(const float4*)(p0 + n * 128);
        float4 k1v = *(const float4*)(p1 + n * 128);
        float4 k2v = *(const float4*)(p2 + n * 128);
        int mk = mp[n];

        float s0 = k0v.x * q0[0].x;            float s1 = k0v.x * q1[0].x;
        s0 = fmaf(k0v.y, q0[0].y, s0);         s1 = fmaf(k0v.y, q1[0].y, s1);
        s0 = fmaf(k0v.z, q0[0].z, s0);         s1 = fmaf(k0v.z, q1[0].z, s1);
        s0 = fmaf(k0v.w, q0[0].w, s0);         s1 = fmaf(k0v.w, q1[0].w, s1);
        s0 = fmaf(k1v.x, q0[1].x, s0);         s1 = fmaf(k1v.x, q1[1].x, s1);
        s0 = fmaf(k1v.y, q0[1].y, s0);         s1 = fmaf(k1v.y, q1[1].y, s1);
        s0 = fmaf(k1v.z, q0[1].z, s0);         s1 = fmaf(k1v.z, q1[1].z, s1);
        s0 = fmaf(k1v.w, q0[1].w, s0);         s1 = fmaf(k1v.w, q1[1].w, s1);
        s0 = fmaf(k2v.x, q0[2].x, s0);         s1 = fmaf(k2v.x, q1[2].x, s1);
        s0 = fmaf(k2v.y, q0[2].y, s0);         s1 = fmaf(k2v.y, q1[2].y, s1);
        s0 = fmaf(k2v.z, q0[2].z, s0);         s1 = fmaf(k2v.z, q1[2].z, s1);
        s0 = fmaf(k2v.w, q0[2].w, s0);         s1 = fmaf(k2v.w, q1[2].w, s1);

        #pragma unroll
        for (int o = 16; o; o >>= 1) {
            s0 += __shfl_xor_sync(0xffffffffu, s0, o);
            s1 += __shfl_xor_sync(0xffffffffu, s1, o);
        }
        s0 *= SCALE;
        s1 *= SCALE;
        if (mk != 0) { s0 = -1e10f; s1 = -1e10f; }

        if ((n & 31) == lane) {
            lg0[n >> 5] = s0;
            lg1[n >> 5] = s1;
        }

        float nm0 = fmaxf(m0, s0);
        float r0  = __expf(m0 - nm0);
        float e0  = __expf(s0 - nm0);
        m0 = nm0;
        l0 = fmaf(l0, r0, e0);
        c0[0].x = fmaf(e0, k0v.x, c0[0].x * r0);
        c0[0].y = fmaf(e0, k0v.y, c0[0].y * r0);
        c0[0].z = fmaf(e0, k0v.z, c0[0].z * r0);
        c0[0].w = fmaf(e0, k0v.w, c0[0].w * r0);
        c0[1].x = fmaf(e0, k1v.x, c0[1].x * r0);
        c0[1].y = fmaf(e0, k1v.y, c0[1].y * r0);
        c0[1].z = fmaf(e0, k1v.z, c0[1].z * r0);
        c0[1].w = fmaf(e0, k1v.w, c0[1].w * r0);
        c0[2].x = fmaf(e0, k2v.x, c0[2].x * r0);
        c0[2].y = fmaf(e0, k2v.y, c0[2].y * r0);
        c0[2].z = fmaf(e0, k2v.z, c0[2].z * r0);
        c0[2].w = fmaf(e0, k2v.w, c0[2].w * r0);

        float nm1 = fmaxf(m1, s1);
        float r1  = __expf(m1 - nm1);
        float e1  = __expf(s1 - nm1);
        m1 = nm1;
        l1 = fmaf(l1, r1, e1);
        c1[0].x = fmaf(e1, k0v.x, c1[0].x * r1);
        c1[0].y = fmaf(e1, k0v.y, c1[0].y * r1);
        c1[0].z = fmaf(e1, k0v.z, c1[0].z * r1);
        c1[0].w = fmaf(e1, k0v.w, c1[0].w * r1);
        c1[1].x = fmaf(e1, k1v.x, c1[1].x * r1);
        c1[1].y = fmaf(e1, k1v.y, c1[1].y * r1);
        c1[1].z = fmaf(e1, k1v.z, c1[1].z * r1);
        c1[1].w = fmaf(e1, k1v.w, c1[1].w * r1);
        c1[2].x = fmaf(e1, k2v.x, c1[2].x * r1);
        c1[2].y = fmaf(e1, k2v.y, c1[2].y * r1);
        c1[2].z = fmaf(e1, k2v.z, c1[2].z * r1);
        c1[2].w = fmaf(e1, k2v.w, c1[2].w * r1);
    }

    const float inv0 = 1.f / l0;
    const float inv1 = 1.f / l1;

    {
        float* cp = ctx + b * 768 + lane * 4;
        #pragma unroll
        for (int it = 0; it < 3; it++) {
            float4 v0 = c0[it];
            v0.x *= inv0; v0.y *= inv0; v0.z *= inv0; v0.w *= inv0;
            *(float4*)(cp + it * 128) = v0;
            float4 v1 = c1[it];
            v1.x *= inv1; v1.y *= inv1; v1.z *= inv1; v1.w *= inv1;
            *(float4*)(cp + 384 + it * 128) = v1;
        }
    }

    attn_out[b * 64 + lane]                     = __expf(lg0[0] - m0) * inv0;
    attn_out[b * 64 + 32 + lane]                = __expf(lg0[1] - m0) * inv0;
    attn_out[((long)Bsz + b) * 64 + lane]       = __expf(lg1[0] - m1) * inv1;
    attn_out[((long)Bsz + b) * 64 + 32 + lane]  = __expf(lg1[1] - m1) * inv1;
}

// ---------------------------------------------------------------------------
// res = sum of 4 out-slabs + bo + q0 ; LayerNorm(384) ; x = [ln_out | src]
// ---------------------------------------------------------------------------
__global__ void ln_kernel(const float* __restrict__ outp,
                          const float* __restrict__ bo,
                          const float* __restrict__ src,
                          const float* __restrict__ src_t,
                          const float* __restrict__ g,
                          const float* __restrict__ bta,
                          float* __restrict__ x)
{
    const size_t SLAB = (size_t)Bsz * 384;
    int wid = threadIdx.x >> 5, lane = threadIdx.x & 31;
    long b = (long)blockIdx.x * 8 + wid;
    float r[12];
    float sum = 0.f, sq = 0.f;
    #pragma unroll
    for (int i = 0; i < 12; i++) {
        int m = lane + i * 32;
        size_t idx = b * 384 + m;
        float v = outp[idx] + outp[idx + SLAB] + outp[idx + 2 * SLAB]
                + outp[idx + 3 * SLAB] + bo[m];
        if (i < 4)       v += src[b * 128 + m];
        else if (i >= 8) v += src_t[b * 128 + (m - 256)];
        r[i] = v;
        sum += v;
        sq  = fmaf(v, v, sq);
    }
    #pragma unroll
    for (int o = 16; o; o >>= 1) {
        sum += __shfl_xor_sync(0xffffffffu, sum, o);
        sq  += __shfl_xor_sync(0xffffffffu, sq, o);
    }
    float mu  = sum * (1.f / 384.f);
    float var = sq * (1.f / 384.f) - mu * mu;
    float inv = rsqrtf(var + 1e-5f);
    #pragma unroll
    for (int i = 0; i < 12; i++) {
        int m = lane + i * 32;
        x[b * 512 + m] = (r[i] - mu) * inv * g[m] + bta[m];
    }
    #pragma unroll
    for (int i = 0; i < 4; i++) {
        int m = lane + i * 32;
        x[b * 512 + 384 + m] = src[b * 128 + m];
    }
}

// ---------------------------------------------------------------------------

extern "C" void kernel_launch(void* const* d_in, const int* in_sizes, int n_in,
                              void* d_out, int out_size)
{
    const float* src   = (const float*)d_in[0];
    const float* src_t = (const float*)d_in[1];
    const float* seq   = (const float*)d_in[2];
    const float* seq_t = (const float*)d_in[3];
    const float* seq_e = (const float*)d_in[4];
    const int*   mask  = (const int*)d_in[5];
    const float* Wq   = (const float*)d_in[6];
    const float* Wk   = (const float*)d_in[7];
    const float* Wv   = (const float*)d_in[8];
    const float* Wo   = (const float*)d_in[9];
    const float* bo   = (const float*)d_in[10];
    const float* ln_g = (const float*)d_in[11];
    const float* ln_b = (const float*)d_in[12];
    const float* W1   = (const float*)d_in[13];
    const float* b1   = (const float*)d_in[14];
    const float* W2   = (const float*)d_in[15];
    const float* b2   = (const float*)d_in[16];

    float* y        = (float*)d_out;
    float* attn_out = (float*)d_out + Bsz * 128;

    float *p_wqk, *p_wov, *p_qk, *p_ctx, *p_out, *p_x, *p_h;
    cudaGetSymbolAddress((void**)&p_wqk, g_wqk);
    cudaGetSymbolAddress((void**)&p_wov, g_wov);
    cudaGetSymbolAddress((void**)&p_qk,  g_qk);
    cudaGetSymbolAddress((void**)&p_ctx, g_ctx);
    cudaGetSymbolAddress((void**)&p_out, g_out);
    cudaGetSymbolAddress((void**)&p_x,   g_x);
    cudaGetSymbolAddress((void**)&p_h,   g_h);

    // 1. folds (merged, one launch)
    fold_both_kernel<<<1920, dim3(16, 16)>>>(Wk, Wq, Wo, Wv, p_wqk, p_wov);

    // 2. qk slabs = [src|src_t] @ Wqk^T   (split-K=2 -> 384 CTAs)
    gemm_nt_128x128<<<dim3(768 / 128, Bsz / 128, 2), 256>>>(
        src, src_t, p_wqk, nullptr, p_qk, Bsz, 768, 256, 0);

    // 3. flash attention (combines qk slabs in the q-load)
    attn_flash_kernel<<<Bsz / 4, 128>>>(seq, seq_e, seq_t, mask, p_qk, p_ctx, attn_out);

    // 4. out slabs = ctx @ Wov^T   (split-K=4 -> 384 CTAs)  [profiled launch]
    gemm_nt_128x128<<<dim3(384 / 128, Bsz / 128, 4), 256>>>(
        p_ctx, nullptr, p_wov, nullptr, p_out, Bsz, 384, 768, 0);

    // 5. residual (4 slabs + bo) + LN + concat
    ln_kernel<<<Bsz / 8, 256>>>(p_out, bo, src, src_t, ln_g, ln_b, p_x);

    // 6. FFN1: h slabs = x @ W1^T (split-K=2 -> 256 CTAs; bias/relu deferred)
    gemm_nt_64<<<dim3(2, Bsz / 64, 2), 256>>>(p_x, nullptr, nullptr, W1, nullptr,
                                              p_h, Bsz, 128, 512, 0);

    // 7. FFN2: y = relu(h0+h1+b1) @ W2^T + b2   (A-combine mode)
    gemm_nt_64<<<dim3(2, Bsz / 64, 1), 256>>>(p_h, p_h + (size_t)Bsz * 128, b1,
                                              W2, b2, y, Bsz, 128, 128, 0);
}

// round 7
// speedup vs baseline: 1.8804x; 1.1632x over previous
#include <cuda_runtime.h>
#include <cuda_bf16.h>

// ---------------------------------------------------------------------------
// TGAT restructured (math unchanged):
//   qk = [src|src_t] @ Wqk^T        (concat A-load; 384 CTAs)
//   flash attention, 1 warp/batch, online softmax, zero smem
//   out = ctx @ Wov^T               split-K=2, slabs + bo summed in LN
//   res=out+q0 ; LN ; x=[ln,src]
//   h-slabs = x @ W1^T (split-K=4); FFN2 A-load = relu(sum h_z + b1); y = .. @ W2^T + b2
// ---------------------------------------------------------------------------

#define Bsz 4096

__device__ __align__(16) float g_wqk[768 * 256];
__device__ __align__(16) float g_wov[384 * 768];
__device__ __align__(16) float g_qk [2 * Bsz * 768];   // attn sums 2 slabs (qk split not used; kept for safety)
__device__ __align__(16) float g_ctx[Bsz * 768];
__device__ __align__(16) float g_out[2 * Bsz * 384];   // split-K=2 slabs
__device__ __align__(16) float g_x  [Bsz * 512];
__device__ __align__(16) float g_h  [4 * Bsz * 128];   // split-K=4 slabs

// ---------------------------------------------------------------------------
// Combined folds (one launch):
//   blocks [0,768):    Wqk[r,c] = sum_d Wk[h*192+d, mloc] * Wq[h*192+d, m'(c)]
//   blocks [768,1920): Wov[j,c] = sum_d Wo[j, h*192+d] * Wv[h*192+d, m0]
// ---------------------------------------------------------------------------
__global__ void fold_both_kernel(const float* __restrict__ Wk,
                                 const float* __restrict__ Wq,
                                 const float* __restrict__ Wo,
                                 const float* __restrict__ Wv,
                                 float* __restrict__ Wqk,
                                 float* __restrict__ Wov)
{
    __shared__ float sA[16][16];
    __shared__ float sB[16][16];
    int tx = threadIdx.x, ty = threadIdx.y;
    int bid = blockIdx.x;
    if (bid < 768) {
        int c0 = (bid & 15) * 16;
        int r0 = (bid >> 4) * 16;
        int h    = r0 / 384;
        int mloc = r0 % 384;
        int c = c0 + tx;
        int mprime = (c < 128) ? c : c + 128;
        float acc = 0.f;
        for (int dt = 0; dt < 192; dt += 16) {
            int d = h * 192 + dt + ty;
            sA[ty][tx] = Wk[d * 384 + (mloc + tx)];
            sB[ty][tx] = Wq[d * 384 + mprime];
            __syncthreads();
            #pragma unroll
            for (int kk = 0; kk < 16; kk++)
                acc = fmaf(sA[kk][ty], sB[kk][tx], acc);
            __syncthreads();
        }
        Wqk[(r0 + ty) * 256 + c0 + tx] = acc;
    } else {
        int b2 = bid - 768;
        int c0 = (b2 % 48) * 16;
        int r0 = (b2 / 48) * 16;
        int h  = c0 / 384;
        int m0 = c0 % 384;
        float acc = 0.f;
        for (int dt = 0; dt < 192; dt += 16) {
            sA[ty][tx] = Wo[(r0 + ty) * 384 + (h * 192 + dt + tx)];
            sB[ty][tx] = Wv[(h * 192 + dt + ty) * 384 + (m0 + tx)];
            __syncthreads();
            #pragma unroll
            for (int kk = 0; kk < 16; kk++)
                acc = fmaf(sA[ty][kk], sB[kk][tx], acc);
            __syncthreads();
        }
        Wov[(r0 + ty) * 768 + c0 + tx] = acc;
    }
}

// ---------------------------------------------------------------------------
// fp32 NT GEMM: 128x64 tile, BK=16, 256 threads, 8x4 micro, double-buffered.
// (Proven R3 config: ~79 regs, no spill.)
// Concat mode: if A1 != nullptr, logical A row = [A0 row(128) | A1 row(128)].
// Split-K via gridDim.z; output slab z at C + z*M*N.
// ---------------------------------------------------------------------------
__global__ void gemm_nt_128x64(const float* __restrict__ A0,
                               const float* __restrict__ A1,
                               const float* __restrict__ B,
                               float* __restrict__ C,
                               int M, int N, int K)
{
    __shared__ float As[2][16][128];
    __shared__ float Bs[2][16][64];
    const int tid  = threadIdx.x;
    const int row0 = blockIdx.y * 128;
    const int col0 = blockIdx.x * 64;
    const int Kslice = K / gridDim.z;
    const int kbase  = blockIdx.z * Kslice;
    float* Cz = C + (size_t)blockIdx.z * (size_t)M * N;

    // A loader: 2 float4/thread
    const int arow  = tid >> 1;
    const int akoff = (tid & 1) << 3;
    // B loader: 1 float4/thread
    const int brow  = tid >> 2;
    const int bkoff = (tid & 3) << 2;
    const float* Bp = B + (long)(col0 + brow) * K + kbase + bkoff;

    const int tr = (tid >> 4) << 3;   // 0..120
    const int tc = (tid & 15) << 2;   // 0..60

    float acc[8][4] = {};

    float4 a0, a1, b0;

    auto loadA = [&](int k) {
        int kk = kbase + k + akoff;
        long row = row0 + arow;
        const float* p;
        if (A1) p = (kk < 128) ? (A0 + row * 128 + kk)
                               : (A1 + row * 128 + (kk - 128));
        else    p = A0 + row * (long)K + kk;
        a0 = *(const float4*)p;
        a1 = *(const float4*)(p + 4);
    };
    auto loadB = [&](int k) {
        b0 = *(const float4*)(Bp + k);
    };
    auto stAB = [&](int buf) {
        As[buf][akoff + 0][arow] = a0.x; As[buf][akoff + 1][arow] = a0.y;
        As[buf][akoff + 2][arow] = a0.z; As[buf][akoff + 3][arow] = a0.w;
        As[buf][akoff + 4][arow] = a1.x; As[buf][akoff + 5][arow] = a1.y;
        As[buf][akoff + 6][arow] = a1.z; As[buf][akoff + 7][arow] = a1.w;
        Bs[buf][bkoff + 0][brow] = b0.x; Bs[buf][bkoff + 1][brow] = b0.y;
        Bs[buf][bkoff + 2][brow] = b0.z; Bs[buf][bkoff + 3][brow] = b0.w;
    };

    loadA(0); loadB(0);
    stAB(0);
    __syncthreads();

    int buf = 0;
    for (int k0 = 0; k0 < Kslice; k0 += 16) {
        const bool nxt = (k0 + 16) < Kslice;
        if (nxt) { loadA(k0 + 16); loadB(k0 + 16); }
        #pragma unroll
        for (int kk = 0; kk < 16; kk++) {
            float ra[8], rb[4];
            *(float4*)(ra)     = *(const float4*)&As[buf][kk][tr];
            *(float4*)(ra + 4) = *(const float4*)&As[buf][kk][tr + 4];
            *(float4*)(rb)     = *(const float4*)&Bs[buf][kk][tc];
            #pragma unroll
            for (int i = 0; i < 8; i++)
                #pragma unroll
                for (int j = 0; j < 4; j++)
                    acc[i][j] = fmaf(ra[i], rb[j], acc[i][j]);
        }
        if (nxt) {
            buf ^= 1;
            stAB(buf);
            __syncthreads();
        }
    }

    #pragma unroll
    for (int i = 0; i < 8; i++) {
        long r = row0 + tr + i;
        *(float4*)(Cz + r * N + col0 + tc) = *(float4*)(acc[i]);
    }
}

// ---------------------------------------------------------------------------
// Small fp32 NT GEMM (64x64, 4x4) with A-combine mode:
//   if nslabs > 1:  A(i,k) = relu(sum_z A[z](i,k) + ab[k])
// ---------------------------------------------------------------------------
__global__ void gemm_nt_64(const float* __restrict__ A,
                           int nslabs, size_t slabStride,
                           const float* __restrict__ ab,
                           const float* __restrict__ B,
                           const float* __restrict__ bias,
                           float* __restrict__ C,
                           int M, int N, int K)
{
    __shared__ float As[16][64];
    __shared__ float Bs[16][64];
    int tid = threadIdx.x;
    int row0 = blockIdx.y * 64;
    int col0 = blockIdx.x * 64;

    int lr = tid >> 2;
    int lk = (tid & 3) << 2;
    int tr = tid >> 4;
    int tc = tid & 15;
    float acc[4][4] = {};
    const float* Ap = A + (long)(row0 + lr) * K + lk;
    const float* Bp = B + (long)(col0 + lr) * K + lk;
    for (int k0 = 0; k0 < K; k0 += 16) {
        float4 a = *(const float4*)(Ap + k0);
        if (nslabs > 1) {
            #pragma unroll 3
            for (int z = 1; z < nslabs; z++) {
                float4 a2 = *(const float4*)(Ap + z * slabStride + k0);
                a.x += a2.x; a.y += a2.y; a.z += a2.z; a.w += a2.w;
            }
            float4 av = *(const float4*)(ab + lk + k0);
            a.x = fmaxf(a.x + av.x, 0.f);
            a.y = fmaxf(a.y + av.y, 0.f);
            a.z = fmaxf(a.z + av.z, 0.f);
            a.w = fmaxf(a.w + av.w, 0.f);
        }
        float4 bq = *(const float4*)(Bp + k0);
        As[lk + 0][lr] = a.x;  As[lk + 1][lr] = a.y;
        As[lk + 2][lr] = a.z;  As[lk + 3][lr] = a.w;
        Bs[lk + 0][lr] = bq.x; Bs[lk + 1][lr] = bq.y;
        Bs[lk + 2][lr] = bq.z; Bs[lk + 3][lr] = bq.w;
        __syncthreads();
        #pragma unroll
        for (int kk = 0; kk < 16; kk++) {
            float av[4], bvv[4];
            #pragma unroll
            for (int i = 0; i < 4; i++) av[i] = As[kk][tr * 4 + i];
            #pragma unroll
            for (int j = 0; j < 4; j++) bvv[j] = Bs[kk][tc * 4 + j];
            #pragma unroll
            for (int i = 0; i < 4; i++)
                #pragma unroll
                for (int j = 0; j < 4; j++)
                    acc[i][j] = fmaf(av[i], bvv[j], acc[i][j]);
        }
        __syncthreads();
    }
    #pragma unroll
    for (int i = 0; i < 4; i++) {
        long r = row0 + tr * 4 + i;
        #pragma unroll
        for (int j = 0; j < 4; j++) {
            int c = col0 + tc * 4 + j;
            float v = acc[i][j];
            if (bias) v += bias[c];
            C[r * N + c] = v;
        }
    }
}

// ---------------------------------------------------------------------------
// Flash attention: 1 warp per batch, zero smem, single pass over k0.
// ---------------------------------------------------------------------------
__global__ void __launch_bounds__(128)
attn_flash_kernel(const float* __restrict__ seq,
                  const float* __restrict__ seq_e,
                  const float* __restrict__ seq_t,
                  const int* __restrict__ mask,
                  const float* __restrict__ qk,
                  float* __restrict__ ctx,
                  float* __restrict__ attn_out)
{
    const int lane = threadIdx.x & 31;
    const long b = (long)blockIdx.x * 4 + (threadIdx.x >> 5);

    float4 q0[3], q1[3];
    {
        const float* qp = qk + b * 768 + lane * 4;
        #pragma unroll
        for (int it = 0; it < 3; it++) {
            q0[it] = *(const float4*)(qp + it * 128);
            q1[it] = *(const float4*)(qp + 384 + it * 128);
        }
    }

    float4 c0[3], c1[3];
    #pragma unroll
    for (int it = 0; it < 3; it++) {
        c0[it] = make_float4(0.f, 0.f, 0.f, 0.f);
        c1[it] = make_float4(0.f, 0.f, 0.f, 0.f);
    }
    float m0 = -1e30f, m1 = -1e30f, l0 = 0.f, l1 = 0.f;
    float lg0[2], lg1[2];

    const float* p0 = seq   + b * 64 * 128 + lane * 4;
    const float* p1 = seq_e + b * 64 * 128 + lane * 4;
    const float* p2 = seq_t + b * 64 * 128 + lane * 4;
    const int*   mp = mask + b * 64;

    const float SCALE = 0.07216878364870323f;   // 1/sqrt(192)

    #pragma unroll 4
    for (int n = 0; n < 64; n++) {
        float4 k0v = *(const float4*)(p0 + n * 128);
        float4 k1v = *(const float4*)(p1 + n * 128);
        float4 k2v = *(const float4*)(p2 + n * 128);
        int mk = mp[n];

        float s0 = k0v.x * q0[0].x;            float s1 = k0v.x * q1[0].x;
        s0 = fmaf(k0v.y, q0[0].y, s0);         s1 = fmaf(k0v.y, q1[0].y, s1);
        s0 = fmaf(k0v.z, q0[0].z, s0);         s1 = fmaf(k0v.z, q1[0].z, s1);
        s0 = fmaf(k0v.w, q0[0].w, s0);         s1 = fmaf(k0v.w, q1[0].w, s1);
        s0 = fmaf(k1v.x, q0[1].x, s0);         s1 = fmaf(k1v.x, q1[1].x, s1);
        s0 = fmaf(k1v.y, q0[1].y, s0);         s1 = fmaf(k1v.y, q1[1].y, s1);
        s0 = fmaf(k1v.z, q0[1].z, s0);         s1 = fmaf(k1v.z, q1[1].z, s1);
        s0 = fmaf(k1v.w, q0[1].w, s0);         s1 = fmaf(k1v.w, q1[1].w, s1);
        s0 = fmaf(k2v.x, q0[2].x, s0);         s1 = fmaf(k2v.x, q1[2].x, s1);
        s0 = fmaf(k2v.y, q0[2].y, s0);         s1 = fmaf(k2v.y, q1[2].y, s1);
        s0 = fmaf(k2v.z, q0[2].z, s0);         s1 = fmaf(k2v.z, q1[2].z, s1);
        s0 = fmaf(k2v.w, q0[2].w, s0);         s1 = fmaf(k2v.w, q1[2].w, s1);

        #pragma unroll
        for (int o = 16; o; o >>= 1) {
            s0 += __shfl_xor_sync(0xffffffffu, s0, o);
            s1 += __shfl_xor_sync(0xffffffffu, s1, o);
        }
        s0 *= SCALE;
        s1 *= SCALE;
        if (mk != 0) { s0 = -1e10f; s1 = -1e10f; }

        if ((n & 31) == lane) {
            lg0[n >> 5] = s0;
            lg1[n >> 5] = s1;
        }

        float nm0 = fmaxf(m0, s0);
        float r0  = __expf(m0 - nm0);
        float e0  = __expf(s0 - nm0);
        m0 = nm0;
        l0 = fmaf(l0, r0, e0);
        c0[0].x = fmaf(e0, k0v.x, c0[0].x * r0);
        c0[0].y = fmaf(e0, k0v.y, c0[0].y * r0);
        c0[0].z = fmaf(e0, k0v.z, c0[0].z * r0);
        c0[0].w = fmaf(e0, k0v.w, c0[0].w * r0);
        c0[1].x = fmaf(e0, k1v.x, c0[1].x * r0);
        c0[1].y = fmaf(e0, k1v.y, c0[1].y * r0);
        c0[1].z = fmaf(e0, k1v.z, c0[1].z * r0);
        c0[1].w = fmaf(e0, k1v.w, c0[1].w * r0);
        c0[2].x = fmaf(e0, k2v.x, c0[2].x * r0);
        c0[2].y = fmaf(e0, k2v.y, c0[2].y * r0);
        c0[2].z = fmaf(e0, k2v.z, c0[2].z * r0);
        c0[2].w = fmaf(e0, k2v.w, c0[2].w * r0);

        float nm1 = fmaxf(m1, s1);
        float r1  = __expf(m1 - nm1);
        float e1  = __expf(s1 - nm1);
        m1 = nm1;
        l1 = fmaf(l1, r1, e1);
        c1[0].x = fmaf(e1, k0v.x, c1[0].x * r1);
        c1[0].y = fmaf(e1, k0v.y, c1[0].y * r1);
        c1[0].z = fmaf(e1, k0v.z, c1[0].z * r1);
        c1[0].w = fmaf(e1, k0v.w, c1[0].w * r1);
        c1[1].x = fmaf(e1, k1v.x, c1[1].x * r1);
        c1[1].y = fmaf(e1, k1v.y, c1[1].y * r1);
        c1[1].z = fmaf(e1, k1v.z, c1[1].z * r1);
        c1[1].w = fmaf(e1, k1v.w, c1[1].w * r1);
        c1[2].x = fmaf(e1, k2v.x, c1[2].x * r1);
        c1[2].y = fmaf(e1, k2v.y, c1[2].y * r1);
        c1[2].z = fmaf(e1, k2v.z, c1[2].z * r1);
        c1[2].w = fmaf(e1, k2v.w, c1[2].w * r1);
    }

    const float inv0 = 1.f / l0;
    const float inv1 = 1.f / l1;

    {
        float* cp = ctx + b * 768 + lane * 4;
        #pragma unroll
        for (int it = 0; it < 3; it++) {
            float4 v0 = c0[it];
            v0.x *= inv0; v0.y *= inv0; v0.z *= inv0; v0.w *= inv0;
            *(float4*)(cp + it * 128) = v0;
            float4 v1 = c1[it];
            v1.x *= inv1; v1.y *= inv1; v1.z *= inv1; v1.w *= inv1;
            *(float4*)(cp + 384 + it * 128) = v1;
        }
    }

    attn_out[b * 64 + lane]                     = __expf(lg0[0] - m0) * inv0;
    attn_out[b * 64 + 32 + lane]                = __expf(lg0[1] - m0) * inv0;
    attn_out[((long)Bsz + b) * 64 + lane]       = __expf(lg1[0] - m1) * inv1;
    attn_out[((long)Bsz + b) * 64 + 32 + lane]  = __expf(lg1[1] - m1) * inv1;
}

// ---------------------------------------------------------------------------
// res = out-slab0 + out-slab1 + bo + q0 ; LayerNorm(384) ; x = [ln_out | src]
// ---------------------------------------------------------------------------
__global__ void ln_kernel(const float* __restrict__ outp,
                          const float* __restrict__ bo,
                          const float* __restrict__ src,
                          const float* __restrict__ src_t,
                          const float* __restrict__ g,
                          const float* __restrict__ bta,
                          float* __restrict__ x)
{
    const size_t SLAB = (size_t)Bsz * 384;
    int wid = threadIdx.x >> 5, lane = threadIdx.x & 31;
    long b = (long)blockIdx.x * 8 + wid;
    float r[12];
    float sum = 0.f, sq = 0.f;
    #pragma unroll
    for (int i = 0; i < 12; i++) {
        int m = lane + i * 32;
        size_t idx = b * 384 + m;
        float v = outp[idx] + outp[idx + SLAB] + bo[m];
        if (i < 4)       v += src[b * 128 + m];
        else if (i >= 8) v += src_t[b * 128 + (m - 256)];
        r[i] = v;
        sum += v;
        sq  = fmaf(v, v, sq);
    }
    #pragma unroll
    for (int o = 16; o; o >>= 1) {
        sum += __shfl_xor_sync(0xffffffffu, sum, o);
        sq  += __shfl_xor_sync(0xffffffffu, sq, o);
    }
    float mu  = sum * (1.f / 384.f);
    float var = sq * (1.f / 384.f) - mu * mu;
    float inv = rsqrtf(var + 1e-5f);
    #pragma unroll
    for (int i = 0; i < 12; i++) {
        int m = lane + i * 32;
        x[b * 512 + m] = (r[i] - mu) * inv * g[m] + bta[m];
    }
    #pragma unroll
    for (int i = 0; i < 4; i++) {
        int m = lane + i * 32;
        x[b * 512 + 384 + m] = src[b * 128 + m];
    }
}

// ---------------------------------------------------------------------------

extern "C" void kernel_launch(void* const* d_in, const int* in_sizes, int n_in,
                              void* d_out, int out_size)
{
    const float* src   = (const float*)d_in[0];
    const float* src_t = (const float*)d_in[1];
    const float* seq   = (const float*)d_in[2];
    const float* seq_t = (const float*)d_in[3];
    const float* seq_e = (const float*)d_in[4];
    const int*   mask  = (const int*)d_in[5];
    const float* Wq   = (const float*)d_in[6];
    const float* Wk   = (const float*)d_in[7];
    const float* Wv   = (const float*)d_in[8];
    const float* Wo   = (const float*)d_in[9];
    const float* bo   = (const float*)d_in[10];
    const float* ln_g = (const float*)d_in[11];
    const float* ln_b = (const float*)d_in[12];
    const float* W1   = (const float*)d_in[13];
    const float* b1   = (const float*)d_in[14];
    const float* W2   = (const float*)d_in[15];
    const float* b2   = (const float*)d_in[16];

    float* y        = (float*)d_out;
    float* attn_out = (float*)d_out + Bsz * 128;

    float *p_wqk, *p_wov, *p_qk, *p_ctx, *p_out, *p_x, *p_h;
    cudaGetSymbolAddress((void**)&p_wqk, g_wqk);
    cudaGetSymbolAddress((void**)&p_wov, g_wov);
    cudaGetSymbolAddress((void**)&p_qk,  g_qk);
    cudaGetSymbolAddress((void**)&p_ctx, g_ctx);
    cudaGetSymbolAddress((void**)&p_out, g_out);
    cudaGetSymbolAddress((void**)&p_x,   g_x);
    cudaGetSymbolAddress((void**)&p_h,   g_h);

    // 1. folds (merged, one launch)
    fold_both_kernel<<<1920, dim3(16, 16)>>>(Wk, Wq, Wo, Wv, p_wqk, p_wov);

    // 2. qk = [src|src_t] @ Wqk^T   (4096 x 768, K=256) — 384 CTAs, full wave
    gemm_nt_128x64<<<dim3(768 / 64, Bsz / 128, 1), 256>>>(
        src, src_t, p_wqk, p_qk, Bsz, 768, 256);

    // 3. flash attention
    attn_flash_kernel<<<Bsz / 4, 128>>>(seq, seq_e, seq_t, mask, p_qk, p_ctx, attn_out);

    // 4. out slabs = ctx @ Wov^T   (4096 x 384, K=768), split-K=2 -> 384 CTAs
    gemm_nt_128x64<<<dim3(384 / 64, Bsz / 128, 2), 256>>>(
        p_ctx, nullptr, p_wov, p_out, Bsz, 384, 768);

    // 5. residual (2 slabs + bo) + LN + concat
    ln_kernel<<<Bsz / 8, 256>>>(p_out, bo, src, src_t, ln_g, ln_b, p_x);

    // 6. FFN1: h slabs = x @ W1^T (split-K=4 -> 256 CTAs; bias/relu deferred)
    gemm_nt_128x64<<<dim3(128 / 64, Bsz / 128, 4), 256>>>(
        p_x, nullptr, W1, p_h, Bsz, 128, 512);

    // 7. FFN2: y = relu(sum_z h_z + b1) @ W2^T + b2   (A-combine mode)
    gemm_nt_64<<<dim3(2, Bsz / 64), 256>>>(p_h, 4, (size_t)Bsz * 128, b1,
                                           W2, b2, y, Bsz, 128, 128);
}

// round 8
// speedup vs baseline: 2.0107x; 1.0693x over previous
#include <cuda_runtime.h>
#include <cuda_bf16.h>

// ---------------------------------------------------------------------------
// TGAT restructured (math unchanged):
//   qk = [src|src_t] @ Wqk^T        (concat A-load; 384 CTAs)
//   flash attention, 1 warp/batch, online softmax, zero smem
//   out = ctx @ Wov^T               split-K=2, slabs + bo summed in LN
//   res=out+q0 ; LN ; x=[ln,src]
//   h-slabs = x @ W1^T (split-K=4); FFN2 A-load = relu(sum h_z + b1); y = .. @ W2^T + b2
// GEMM inner loops use packed fma.rn.f32x2 (FFMA2): 2 fp32 FMA per issue slot,
// bit-identical IEEE fp32 per lane.
// ---------------------------------------------------------------------------

#define Bsz 4096

__device__ __align__(16) float g_wqk[768 * 256];
__device__ __align__(16) float g_wov[384 * 768];
__device__ __align__(16) float g_qk [Bsz * 768];
__device__ __align__(16) float g_ctx[Bsz * 768];
__device__ __align__(16) float g_out[2 * Bsz * 384];   // split-K=2 slabs
__device__ __align__(16) float g_x  [Bsz * 512];
__device__ __align__(16) float g_h  [4 * Bsz * 128];   // split-K=4 slabs

// packed f32x2 helpers
#define FFMA2(d, a, b) \
    asm("fma.rn.f32x2 %0, %1, %2, %0;" : "+l"(d) : "l"(a), "l"(b))
__device__ __forceinline__ unsigned long long dupf(float x) {
    unsigned long long d;
    unsigned r = __float_as_uint(x);
    asm("mov.b64 %0, {%1, %1};" : "=l"(d) : "r"(r));
    return d;
}
__device__ __forceinline__ float lo32(unsigned long long v) {
    return __uint_as_float((unsigned)v);
}
__device__ __forceinline__ float hi32(unsigned long long v) {
    return __uint_as_float((unsigned)(v >> 32));
}

// ---------------------------------------------------------------------------
// Combined folds (one launch)
// ---------------------------------------------------------------------------
__global__ void fold_both_kernel(const float* __restrict__ Wk,
                                 const float* __restrict__ Wq,
                                 const float* __restrict__ Wo,
                                 const float* __restrict__ Wv,
                                 float* __restrict__ Wqk,
                                 float* __restrict__ Wov)
{
    __shared__ float sA[16][16];
    __shared__ float sB[16][16];
    int tx = threadIdx.x, ty = threadIdx.y;
    int bid = blockIdx.x;
    if (bid < 768) {
        int c0 = (bid & 15) * 16;
        int r0 = (bid >> 4) * 16;
        int h    = r0 / 384;
        int mloc = r0 % 384;
        int c = c0 + tx;
        int mprime = (c < 128) ? c : c + 128;
        float acc = 0.f;
        for (int dt = 0; dt < 192; dt += 16) {
            int d = h * 192 + dt + ty;
            sA[ty][tx] = Wk[d * 384 + (mloc + tx)];
            sB[ty][tx] = Wq[d * 384 + mprime];
            __syncthreads();
            #pragma unroll
            for (int kk = 0; kk < 16; kk++)
                acc = fmaf(sA[kk][ty], sB[kk][tx], acc);
            __syncthreads();
        }
        Wqk[(r0 + ty) * 256 + c0 + tx] = acc;
    } else {
        int b2 = bid - 768;
        int c0 = (b2 % 48) * 16;
        int r0 = (b2 / 48) * 16;
        int h  = c0 / 384;
        int m0 = c0 % 384;
        float acc = 0.f;
        for (int dt = 0; dt < 192; dt += 16) {
            sA[ty][tx] = Wo[(r0 + ty) * 384 + (h * 192 + dt + tx)];
            sB[ty][tx] = Wv[(h * 192 + dt + ty) * 384 + (m0 + tx)];
            __syncthreads();
            #pragma unroll
            for (int kk = 0; kk < 16; kk++)
                acc = fmaf(sA[ty][kk], sB[kk][tx], acc);
            __syncthreads();
        }
        Wov[(r0 + ty) * 768 + c0 + tx] = acc;
    }
}

// ---------------------------------------------------------------------------
// fp32 NT GEMM: 128x64 tile, BK=16, 256 threads, 8x4 micro, double-buffered,
// FFMA2 inner loop (acc packed over row pairs).
// Concat mode: if A1 != nullptr, logical A row = [A0 row(128) | A1 row(128)].
// Split-K via gridDim.z; output slab z at C + z*M*N.
// ---------------------------------------------------------------------------
__global__ void gemm_nt_128x64(const float* __restrict__ A0,
                               const float* __restrict__ A1,
                               const float* __restrict__ B,
                               float* __restrict__ C,
                               int M, int N, int K)
{
    __shared__ float As[2][16][128];
    __shared__ float Bs[2][16][64];
    const int tid  = threadIdx.x;
    const int row0 = blockIdx.y * 128;
    const int col0 = blockIdx.x * 64;
    const int Kslice = K / gridDim.z;
    const int kbase  = blockIdx.z * Kslice;
    float* Cz = C + (size_t)blockIdx.z * (size_t)M * N;

    const int arow  = tid >> 1;
    const int akoff = (tid & 1) << 3;
    const int brow  = tid >> 2;
    const int bkoff = (tid & 3) << 2;
    const float* Bp = B + (long)(col0 + brow) * K + kbase + bkoff;

    const int tr = (tid >> 4) << 3;   // 0..120
    const int tc = (tid & 15) << 2;   // 0..60

    // acc packed: accp[p][j] holds rows (tr+2p, tr+2p+1), col tc+j
    unsigned long long accp[4][4] = {};

    float4 a0, a1, b0;

    auto loadA = [&](int k) {
        int kk = kbase + k + akoff;
        long row = row0 + arow;
        const float* p;
        if (A1) p = (kk < 128) ? (A0 + row * 128 + kk)
                               : (A1 + row * 128 + (kk - 128));
        else    p = A0 + row * (long)K + kk;
        a0 = *(const float4*)p;
        a1 = *(const float4*)(p + 4);
    };
    auto loadB = [&](int k) {
        b0 = *(const float4*)(Bp + k);
    };
    auto stAB = [&](int buf) {
        As[buf][akoff + 0][arow] = a0.x; As[buf][akoff + 1][arow] = a0.y;
        As[buf][akoff + 2][arow] = a0.z; As[buf][akoff + 3][arow] = a0.w;
        As[buf][akoff + 4][arow] = a1.x; As[buf][akoff + 5][arow] = a1.y;
        As[buf][akoff + 6][arow] = a1.z; As[buf][akoff + 7][arow] = a1.w;
        Bs[buf][bkoff + 0][brow] = b0.x; Bs[buf][bkoff + 1][brow] = b0.y;
        Bs[buf][bkoff + 2][brow] = b0.z; Bs[buf][bkoff + 3][brow] = b0.w;
    };

    loadA(0); loadB(0);
    stAB(0);
    __syncthreads();

    int buf = 0;
    for (int k0 = 0; k0 < Kslice; k0 += 16) {
        const bool nxt = (k0 + 16) < Kslice;
        if (nxt) { loadA(k0 + 16); loadB(k0 + 16); }
        #pragma unroll
        for (int kk = 0; kk < 16; kk++) {
            // A fragment: 8 rows = 4 natural b64 pairs
            unsigned long long rap[4];
            *(float4*)(&rap[0]) = *(const float4*)&As[buf][kk][tr];
            *(float4*)(&rap[2]) = *(const float4*)&As[buf][kk][tr + 4];
            // B fragment: 4 cols, duplicated into b64
            float4 rbv = *(const float4*)&Bs[buf][kk][tc];
            unsigned long long bd0 = dupf(rbv.x);
            unsigned long long bd1 = dupf(rbv.y);
            unsigned long long bd2 = dupf(rbv.z);
            unsigned long long bd3 = dupf(rbv.w);
            #pragma unroll
            for (int p = 0; p < 4; p++) {
                FFMA2(accp[p][0], rap[p], bd0);
                FFMA2(accp[p][1], rap[p], bd1);
                FFMA2(accp[p][2], rap[p], bd2);
                FFMA2(accp[p][3], rap[p], bd3);
            }
        }
        if (nxt) {
            buf ^= 1;
            stAB(buf);
            __syncthreads();
        }
    }

    #pragma unroll
    for (int p = 0; p < 4; p++) {
        long r0r = row0 + tr + 2 * p;
        float o0[4], o1[4];
        #pragma unroll
        for (int j = 0; j < 4; j++) {
            o0[j] = lo32(accp[p][j]);
            o1[j] = hi32(accp[p][j]);
        }
        *(float4*)(Cz + r0r * N + col0 + tc)       = *(float4*)(o0);
        *(float4*)(Cz + (r0r + 1) * N + col0 + tc) = *(float4*)(o1);
    }
}

// ---------------------------------------------------------------------------
// Small fp32 NT GEMM (64x64, 4x4, FFMA2) with A-combine mode:
//   if nslabs > 1:  A(i,k) = relu(sum_z A[z](i,k) + ab[k])
// ---------------------------------------------------------------------------
__global__ void gemm_nt_64(const float* __restrict__ A,
                           int nslabs, size_t slabStride,
                           const float* __restrict__ ab,
                           const float* __restrict__ B,
                           const float* __restrict__ bias,
                           float* __restrict__ C,
                           int M, int N, int K)
{
    __shared__ float As[16][64];
    __shared__ float Bs[16][64];
    int tid = threadIdx.x;
    int row0 = blockIdx.y * 64;
    int col0 = blockIdx.x * 64;

    int lr = tid >> 2;
    int lk = (tid & 3) << 2;
    int tr = tid >> 4;
    int tc = tid & 15;
    unsigned long long accp[2][4] = {};   // rows (tr*4+2p, +1), col tc*4+j
    const float* Ap = A + (long)(row0 + lr) * K + lk;
    const float* Bp = B + (long)(col0 + lr) * K + lk;
    for (int k0 = 0; k0 < K; k0 += 16) {
        float4 a = *(const float4*)(Ap + k0);
        if (nslabs > 1) {
            #pragma unroll 3
            for (int z = 1; z < nslabs; z++) {
                float4 a2 = *(const float4*)(Ap + z * slabStride + k0);
                a.x += a2.x; a.y += a2.y; a.z += a2.z; a.w += a2.w;
            }
            float4 av = *(const float4*)(ab + lk + k0);
            a.x = fmaxf(a.x + av.x, 0.f);
            a.y = fmaxf(a.y + av.y, 0.f);
            a.z = fmaxf(a.z + av.z, 0.f);
            a.w = fmaxf(a.w + av.w, 0.f);
        }
        float4 bq = *(const float4*)(Bp + k0);
        As[lk + 0][lr] = a.x;  As[lk + 1][lr] = a.y;
        As[lk + 2][lr] = a.z;  As[lk + 3][lr] = a.w;
        Bs[lk + 0][lr] = bq.x; Bs[lk + 1][lr] = bq.y;
        Bs[lk + 2][lr] = bq.z; Bs[lk + 3][lr] = bq.w;
        __syncthreads();
        #pragma unroll
        for (int kk = 0; kk < 16; kk++) {
            unsigned long long rap[2];
            *(float4*)(&rap[0]) = *(const float4*)&As[kk][tr * 4];
            float4 rbv = *(const float4*)&Bs[kk][tc * 4];
            unsigned long long bd0 = dupf(rbv.x);
            unsigned long long bd1 = dupf(rbv.y);
            unsigned long long bd2 = dupf(rbv.z);
            unsigned long long bd3 = dupf(rbv.w);
            #pragma unroll
            for (int p = 0; p < 2; p++) {
                FFMA2(accp[p][0], rap[p], bd0);
                FFMA2(accp[p][1], rap[p], bd1);
                FFMA2(accp[p][2], rap[p], bd2);
                FFMA2(accp[p][3], rap[p], bd3);
            }
        }
        __syncthreads();
    }
    #pragma unroll
    for (int p = 0; p < 2; p++) {
        long r0r = row0 + tr * 4 + 2 * p;
        #pragma unroll
        for (int j = 0; j < 4; j++) {
            int c = col0 + tc * 4 + j;
            float v0 = lo32(accp[p][j]);
            float v1 = hi32(accp[p][j]);
            if (bias) { v0 += bias[c]; v1 += bias[c]; }
            C[r0r * N + c]       = v0;
            C[(r0r + 1) * N + c] = v1;
        }
    }
}

// ---------------------------------------------------------------------------
// Flash attention: 1 warp per batch, zero smem, single pass over k0.
// ---------------------------------------------------------------------------
__global__ void __launch_bounds__(128)
attn_flash_kernel(const float* __restrict__ seq,
                  const float* __restrict__ seq_e,
                  const float* __restrict__ seq_t,
                  const int* __restrict__ mask,
                  const float* __restrict__ qk,
                  float* __restrict__ ctx,
                  float* __restrict__ attn_out)
{
    const int lane = threadIdx.x & 31;
    const long b = (long)blockIdx.x * 4 + (threadIdx.x >> 5);

    float4 q0[3], q1[3];
    {
        const float* qp = qk + b * 768 + lane * 4;
        #pragma unroll
        for (int it = 0; it < 3; it++) {
            q0[it] = *(const float4*)(qp + it * 128);
            q1[it] = *(const float4*)(qp + 384 + it * 128);
        }
    }

    float4 c0[3], c1[3];
    #pragma unroll
    for (int it = 0; it < 3; it++) {
        c0[it] = make_float4(0.f, 0.f, 0.f, 0.f);
        c1[it] = make_float4(0.f, 0.f, 0.f, 0.f);
    }
    float m0 = -1e30f, m1 = -1e30f, l0 = 0.f, l1 = 0.f;
    float lg0[2], lg1[2];

    const float* p0 = seq   + b * 64 * 128 + lane * 4;
    const float* p1 = seq_e + b * 64 * 128 + lane * 4;
    const float* p2 = seq_t + b * 64 * 128 + lane * 4;
    const int*   mp = mask + b * 64;

    const float SCALE = 0.07216878364870323f;   // 1/sqrt(192)

    #pragma unroll 4
    for (int n = 0; n < 64; n++) {
        float4 k0v = *(const float4*)(p0 + n * 128);
        float4 k1v = *(const float4*)(p1 + n * 128);
        float4 k2v = *(const float4*)(p2 + n * 128);
        int mk = mp[n];

        float s0 = k0v.x * q0[0].x;            float s1 = k0v.x * q1[0].x;
        s0 = fmaf(k0v.y, q0[0].y, s0);         s1 = fmaf(k0v.y, q1[0].y, s1);
        s0 = fmaf(k0v.z, q0[0].z, s0);         s1 = fmaf(k0v.z, q1[0].z, s1);
        s0 = fmaf(k0v.w, q0[0].w, s0);         s1 = fmaf(k0v.w, q1[0].w, s1);
        s0 = fmaf(k1v.x, q0[1].x, s0);         s1 = fmaf(k1v.x, q1[1].x, s1);
        s0 = fmaf(k1v.y, q0[1].y, s0);         s1 = fmaf(k1v.y, q1[1].y, s1);
        s0 = fmaf(k1v.z, q0[1].z, s0);         s1 = fmaf(k1v.z, q1[1].z, s1);
        s0 = fmaf(k1v.w, q0[1].w, s0);         s1 = fmaf(k1v.w, q1[1].w, s1);
        s0 = fmaf(k2v.x, q0[2].x, s0);         s1 = fmaf(k2v.x, q1[2].x, s1);
        s0 = fmaf(k2v.y, q0[2].y, s0);         s1 = fmaf(k2v.y, q1[2].y, s1);
        s0 = fmaf(k2v.z, q0[2].z, s0);         s1 = fmaf(k2v.z, q1[2].z, s1);
        s0 = fmaf(k2v.w, q0[2].w, s0);         s1 = fmaf(k2v.w, q1[2].w, s1);

        #pragma unroll
        for (int o = 16; o; o >>= 1) {
            s0 += __shfl_xor_sync(0xffffffffu, s0, o);
            s1 += __shfl_xor_sync(0xffffffffu, s1, o);
        }
        s0 *= SCALE;
        s1 *= SCALE;
        if (mk != 0) { s0 = -1e10f; s1 = -1e10f; }

        if ((n & 31) == lane) {
            lg0[n >> 5] = s0;
            lg1[n >> 5] = s1;
        }

        float nm0 = fmaxf(m0, s0);
        float r0  = __expf(m0 - nm0);
        float e0  = __expf(s0 - nm0);
        m0 = nm0;
        l0 = fmaf(l0, r0, e0);
        c0[0].x = fmaf(e0, k0v.x, c0[0].x * r0);
        c0[0].y = fmaf(e0, k0v.y, c0[0].y * r0);
        c0[0].z = fmaf(e0, k0v.z, c0[0].z * r0);
        c0[0].w = fmaf(e0, k0v.w, c0[0].w * r0);
        c0[1].x = fmaf(e0, k1v.x, c0[1].x * r0);
        c0[1].y = fmaf(e0, k1v.y, c0[1].y * r0);
        c0[1].z = fmaf(e0, k1v.z, c0[1].z * r0);
        c0[1].w = fmaf(e0, k1v.w, c0[1].w * r0);
        c0[2].x = fmaf(e0, k2v.x, c0[2].x * r0);
        c0[2].y = fmaf(e0, k2v.y, c0[2].y * r0);
        c0[2].z = fmaf(e0, k2v.z, c0[2].z * r0);
        c0[2].w = fmaf(e0, k2v.w, c0[2].w * r0);

        float nm1 = fmaxf(m1, s1);
        float r1  = __expf(m1 - nm1);
        float e1  = __expf(s1 - nm1);
        m1 = nm1;
        l1 = fmaf(l1, r1, e1);
        c1[0].x = fmaf(e1, k0v.x, c1[0].x * r1);
        c1[0].y = fmaf(e1, k0v.y, c1[0].y * r1);
        c1[0].z = fmaf(e1, k0v.z, c1[0].z * r1);
        c1[0].w = fmaf(e1, k0v.w, c1[0].w * r1);
        c1[1].x = fmaf(e1, k1v.x, c1[1].x * r1);
        c1[1].y = fmaf(e1, k1v.y, c1[1].y * r1);
        c1[1].z = fmaf(e1, k1v.z, c1[1].z * r1);
        c1[1].w = fmaf(e1, k1v.w, c1[1].w * r1);
        c1[2].x = fmaf(e1, k2v.x, c1[2].x * r1);
        c1[2].y = fmaf(e1, k2v.y, c1[2].y * r1);
        c1[2].z = fmaf(e1, k2v.z, c1[2].z * r1);
        c1[2].w = fmaf(e1, k2v.w, c1[2].w * r1);
    }

    const float inv0 = 1.f / l0;
    const float inv1 = 1.f / l1;

    {
        float* cp = ctx + b * 768 + lane * 4;
        #pragma unroll
        for (int it = 0; it < 3; it++) {
            float4 v0 = c0[it];
            v0.x *= inv0; v0.y *= inv0; v0.z *= inv0; v0.w *= inv0;
            *(float4*)(cp + it * 128) = v0;
            float4 v1 = c1[it];
            v1.x *= inv1; v1.y *= inv1; v1.z *= inv1; v1.w *= inv1;
            *(float4*)(cp + 384 + it * 128) = v1;
        }
    }

    attn_out[b * 64 + lane]                     = __expf(lg0[0] - m0) * inv0;
    attn_out[b * 64 + 32 + lane]                = __expf(lg0[1] - m0) * inv0;
    attn_out[((long)Bsz + b) * 64 + lane]       = __expf(lg1[0] - m1) * inv1;
    attn_out[((long)Bsz + b) * 64 + 32 + lane]  = __expf(lg1[1] - m1) * inv1;
}

// ---------------------------------------------------------------------------
// res = out-slab0 + out-slab1 + bo + q0 ; LayerNorm(384) ; x = [ln_out | src]
// ---------------------------------------------------------------------------
__global__ void ln_kernel(const float* __restrict__ outp,
                          const float* __restrict__ bo,
                          const float* __restrict__ src,
                          const float* __restrict__ src_t,
                          const float* __restrict__ g,
                          const float* __restrict__ bta,
                          float* __restrict__ x)
{
    const size_t SLAB = (size_t)Bsz * 384;
    int wid = threadIdx.x >> 5, lane = threadIdx.x & 31;
    long b = (long)blockIdx.x * 8 + wid;
    float r[12];
    float sum = 0.f, sq = 0.f;
    #pragma unroll
    for (int i = 0; i < 12; i++) {
        int m = lane + i * 32;
        size_t idx = b * 384 + m;
        float v = outp[idx] + outp[idx + SLAB] + bo[m];
        if (i < 4)       v += src[b * 128 + m];
        else if (i >= 8) v += src_t[b * 128 + (m - 256)];
        r[i] = v;
        sum += v;
        sq  = fmaf(v, v, sq);
    }
    #pragma unroll
    for (int o = 16; o; o >>= 1) {
        sum += __shfl_xor_sync(0xffffffffu, sum, o);
        sq  += __shfl_xor_sync(0xffffffffu, sq, o);
    }
    float mu  = sum * (1.f / 384.f);
    float var = sq * (1.f / 384.f) - mu * mu;
    float inv = rsqrtf(var + 1e-5f);
    #pragma unroll
    for (int i = 0; i < 12; i++) {
        int m = lane + i * 32;
        x[b * 512 + m] = (r[i] - mu) * inv * g[m] + bta[m];
    }
    #pragma unroll
    for (int i = 0; i < 4; i++) {
        int m = lane + i * 32;
        x[b * 512 + 384 + m] = src[b * 128 + m];
    }
}

// ---------------------------------------------------------------------------

extern "C" void kernel_launch(void* const* d_in, const int* in_sizes, int n_in,
                              void* d_out, int out_size)
{
    const float* src   = (const float*)d_in[0];
    const float* src_t = (const float*)d_in[1];
    const float* seq   = (const float*)d_in[2];
    const float* seq_t = (const float*)d_in[3];
    const float* seq_e = (const float*)d_in[4];
    const int*   mask  = (const int*)d_in[5];
    const float* Wq   = (const float*)d_in[6];
    const float* Wk   = (const float*)d_in[7];
    const float* Wv   = (const float*)d_in[8];
    const float* Wo   = (const float*)d_in[9];
    const float* bo   = (const float*)d_in[10];
    const float* ln_g = (const float*)d_in[11];
    const float* ln_b = (const float*)d_in[12];
    const float* W1   = (const float*)d_in[13];
    const float* b1   = (const float*)d_in[14];
    const float* W2   = (const float*)d_in[15];
    const float* b2   = (const float*)d_in[16];

    float* y        = (float*)d_out;
    float* attn_out = (float*)d_out + Bsz * 128;

    float *p_wqk, *p_wov, *p_qk, *p_ctx, *p_out, *p_x, *p_h;
    cudaGetSymbolAddress((void**)&p_wqk, g_wqk);
    cudaGetSymbolAddress((void**)&p_wov, g_wov);
    cudaGetSymbolAddress((void**)&p_qk,  g_qk);
    cudaGetSymbolAddress((void**)&p_ctx, g_ctx);
    cudaGetSymbolAddress((void**)&p_out, g_out);
    cudaGetSymbolAddress((void**)&p_x,   g_x);
    cudaGetSymbolAddress((void**)&p_h,   g_h);

    // 1. folds (merged, one launch)
    fold_both_kernel<<<1920, dim3(16, 16)>>>(Wk, Wq, Wo, Wv, p_wqk, p_wov);

    // 2. qk = [src|src_t] @ Wqk^T   (4096 x 768, K=256) — 384 CTAs
    gemm_nt_128x64<<<dim3(768 / 64, Bsz / 128, 1), 256>>>(
        src, src_t, p_wqk, p_qk, Bsz, 768, 256);

    // 3. flash attention
    attn_flash_kernel<<<Bsz / 4, 128>>>(seq, seq_e, seq_t, mask, p_qk, p_ctx, attn_out);

    // 4. out slabs = ctx @ Wov^T   (4096 x 384, K=768), split-K=2 -> 384 CTAs
    gemm_nt_128x64<<<dim3(384 / 64, Bsz / 128, 2), 256>>>(
        p_ctx, nullptr, p_wov, p_out, Bsz, 384, 768);

    // 5. residual (2 slabs + bo) + LN + concat
    ln_kernel<<<Bsz / 8, 256>>>(p_out, bo, src, src_t, ln_g, ln_b, p_x);

    // 6. FFN1: h slabs = x @ W1^T (split-K=4 -> 256 CTAs; bias/relu deferred)
    gemm_nt_128x64<<<dim3(128 / 64, Bsz / 128, 4), 256>>>(
        p_x, nullptr, W1, p_h, Bsz, 128, 512);

    // 7. FFN2: y = relu(sum_z h_z + b1) @ W2^T + b2   (A-combine mode)
    gemm_nt_64<<<dim3(2, Bsz / 64), 256>>>(p_h, 4, (size_t)Bsz * 128, b1,
                                           W2, b2, y, Bsz, 128, 128);
}